// round 1
// baseline (speedup 1.0000x reference)
#include <cuda_runtime.h>
#include <math.h>

#define NB 8
#define ND 128
#define NG 2048
#define NL 24
#define NGF 1025
#define NDD 16384   // D*D

// Scratch (device globals: allocation-free contract)
__device__ float  g_mean[NB*NG];
__device__ float  g_rstd[NB*NG];
__device__ float2 g_Xf[NGF*NB*ND];     // [f][b*128+d]  8.4 MB
__device__ float  g_M [NGF*NDD];       // [f][h][d]     67.1 MB
__device__ float2 g_Sf[NB*ND*NGF];     // [b*128+h][f]  8.4 MB
__device__ float  g_S [NB*ND*NG];      // [b*128+h][g]  8.4 MB

// ---------------------------------------------------------------- LN stats
__global__ void k_lnstats(const float* __restrict__ x) {
    int id = blockIdx.x*256 + threadIdx.x;     // 0..16383 = (b,g)
    int b = id >> 11, g = id & 2047;
    const float* p = x + (size_t)b*ND*NG + g;
    float s = 0.f, ss = 0.f;
    #pragma unroll 8
    for (int d = 0; d < ND; d++) { float v = p[d*NG]; s += v; ss += v*v; }
    float mean = s * (1.f/ND);
    float var  = ss * (1.f/ND) - mean*mean;
    g_mean[id] = mean;
    g_rstd[id] = rsqrtf(var + 1e-5f);
}

// ---------------------------------------------------------------- shared-mem FFT 2048 (256 threads)
__device__ __forceinline__ void fft2048(float* re, float* im, const float2* tw, int inv) {
    int t = threadIdx.x;
    #pragma unroll
    for (int s = 1; s <= 11; s++) {
        int half = 1 << (s-1);
        __syncthreads();
        #pragma unroll
        for (int j = 0; j < 4; j++) {
            int k   = t + j*256;
            int pos = k & (half-1);
            int i0  = ((k >> (s-1)) << s) + pos;
            int i1  = i0 + half;
            float2 w = tw[pos << (11-s)];
            float wy = inv ? -w.y : w.y;
            float xr = re[i1], xi = im[i1];
            float tr = w.x*xr - wy*xi;
            float ti = w.x*xi + wy*xr;
            float ar = re[i0], ai = im[i0];
            re[i0] = ar + tr; im[i0] = ai + ti;
            re[i1] = ar - tr; im[i1] = ai - ti;
        }
    }
    __syncthreads();
}

// ---------------------------------------------------------------- forward: LN-apply + packed real FFT (2 rows/block)
__global__ void k_fft_fwd(const float* __restrict__ x,
                          const float* __restrict__ gamma,
                          const float* __restrict__ beta) {
    __shared__ float re[2048], im[2048];
    __shared__ float2 tw[1024];
    int t = threadIdx.x;
    int row0 = blockIdx.x*2, row1 = row0 + 1;
    int b = row0 >> 7;
    int d0 = row0 & 127, d1 = d0 + 1;
    for (int j = t; j < 1024; j += 256) {
        float sv, cv;
        sincosf(-6.2831853071795864769f * (float)j * (1.f/2048.f), &sv, &cv);
        tw[j] = make_float2(cv, sv);
    }
    const float* xp0 = x + (size_t)row0*NG;
    const float* xp1 = x + (size_t)row1*NG;
    const float* mp  = g_mean + b*NG;
    const float* rp  = g_rstd + b*NG;
    float ga0 = gamma[d0], be0 = beta[d0], ga1 = gamma[d1], be1 = beta[d1];
    #pragma unroll
    for (int j = 0; j < 8; j++) {
        int i = t + j*256;
        float m = mp[i], r = rp[i];
        float z0 = (xp0[i]-m)*r*ga0 + be0;
        float z1 = (xp1[i]-m)*r*ga1 + be1;
        int rv = __brev(i) >> 21;
        re[rv] = z0; im[rv] = z1;            // z0 + i*z1
    }
    fft2048(re, im, tw, 0);
    // unpack two real spectra from one complex FFT
    #pragma unroll
    for (int j = 0; j < 5; j++) {
        int k = t + j*256;
        if (k <= 1024) {
            int km = (2048 - k) & 2047;
            float zr = re[k], zi = im[k];
            float mr = re[km], mi = im[km];
            float2 A  = make_float2(0.5f*(zr+mr), 0.5f*(zi-mi));
            float2 Bv = make_float2(0.5f*(zi+mi), 0.5f*(mr-zr));
            g_Xf[k*(NB*ND) + row0] = A;
            g_Xf[k*(NB*ND) + row1] = Bv;
        }
    }
}

// ---------------------------------------------------------------- M[f,h,d] = sum_l Phi[l,f]*Theta[l,h,d]   (16 f per block)
__global__ void k_build_M(const float* __restrict__ Phi, const float* __restrict__ Theta) {
    __shared__ float sphi[NL*16];
    int t  = threadIdx.x;
    int i  = blockIdx.x*256 + t;      // h*128+d
    int f0 = blockIdx.y*16;
    for (int idx = t; idx < NL*16; idx += 256) {
        int l = idx >> 4, ff = idx & 15;
        sphi[idx] = (f0+ff < NGF) ? Phi[l*NGF + f0 + ff] : 0.f;
    }
    __syncthreads();
    float acc[16];
    #pragma unroll
    for (int j = 0; j < 16; j++) acc[j] = 0.f;
    #pragma unroll 4
    for (int l = 0; l < NL; l++) {
        float th = Theta[l*NDD + i];
        #pragma unroll
        for (int j = 0; j < 16; j++) acc[j] += sphi[l*16+j]*th;
    }
    #pragma unroll
    for (int j = 0; j < 16; j++)
        if (f0+j < NGF) g_M[(size_t)(f0+j)*NDD + i] = acc[j];
}

// ---------------------------------------------------------------- S_f[b,h,f] = sum_d M[f,h,d]*Xf[b,d,f]
__global__ void k_sf() {
    __shared__ float Msh[32*129];
    __shared__ float sXr[1024], sXi[1024];
    int t = threadIdx.x;       // 256
    int f = blockIdx.x;
    for (int idx = t; idx < 1024; idx += 256) {
        float2 v = g_Xf[f*1024 + idx];
        int bb = idx >> 7, dd = idx & 127;
        sXr[dd*8 + bb] = v.x;
        sXi[dd*8 + bb] = v.y;
    }
    int b = t & 7, h0 = t >> 3;
    const float* Mbase = g_M + (size_t)f*NDD;
    for (int c = 0; c < 4; c++) {
        __syncthreads();
        for (int idx = t; idx < 4096; idx += 256) {
            int hh = idx >> 7, dd = idx & 127;
            Msh[hh*129 + dd] = Mbase[c*4096 + idx];
        }
        __syncthreads();
        float ar = 0.f, ai = 0.f;
        const float* mrow = Msh + h0*129;
        #pragma unroll 8
        for (int d = 0; d < 128; d++) {
            float m = mrow[d];
            ar += m * sXr[d*8+b];
            ai += m * sXi[d*8+b];
        }
        int h = c*32 + h0;
        g_Sf[(b*ND + h)*NGF + f] = make_float2(ar, ai);
    }
}

// ---------------------------------------------------------------- packed irfft: ifft(S1 + i*S2) -> two real rows
__global__ void k_ifft() {
    __shared__ float re[2048], im[2048];
    __shared__ float2 tw[1024];
    int t = threadIdx.x;
    int row0 = blockIdx.x*2, row1 = row0 + 1;
    for (int j = t; j < 1024; j += 256) {
        float sv, cv;
        sincosf(-6.2831853071795864769f * (float)j * (1.f/2048.f), &sv, &cv);
        tw[j] = make_float2(cv, sv);
    }
    const float2* p0 = g_Sf + (size_t)row0*NGF;
    const float2* p1 = g_Sf + (size_t)row1*NGF;
    #pragma unroll
    for (int j = 0; j < 8; j++) {
        int i = t + j*256;
        int src = (i <= 1024) ? i : 2048 - i;
        float2 v0 = p0[src], v1 = p1[src];
        if (i > 1024) { v0.y = -v0.y; v1.y = -v1.y; }   // Hermitian mirror
        int rv = __brev(i) >> 21;
        re[rv] = v0.x - v1.y;      // Z = S1 + i*S2
        im[rv] = v0.y + v1.x;
    }
    fft2048(re, im, tw, 1);
    const float sc = 1.0f/2048.0f;
    #pragma unroll
    for (int j = 0; j < 8; j++) {
        int i = t + j*256;
        g_S[(size_t)row0*NG + i] = re[i]*sc;
        g_S[(size_t)row1*NG + i] = im[i]*sc;
    }
}

// ---------------------------------------------------------------- fused MLP + residual (g-tile 16, 128 threads)
__global__ void k_mlp(const float* __restrict__ x,
                      const float* __restrict__ w1, const float* __restrict__ b1,
                      const float* __restrict__ w2, const float* __restrict__ b2,
                      float* __restrict__ out) {
    __shared__ float Ssh[128*16];
    __shared__ float Hsh[256*20];   // stride 20 floats (16B-aligned rows, low bank conflict)
    int t  = threadIdx.x;           // 128
    int b  = blockIdx.y;
    int g0 = blockIdx.x * 16;
    for (int idx = t; idx < 128*16; idx += 128) {
        int d = idx >> 4, g = idx & 15;
        Ssh[idx] = g_S[(size_t)(b*ND + d)*NG + g0 + g];
    }
    __syncthreads();
    // fc1: thread computes rows t and t+128
    float a0[16], a1[16];
    #pragma unroll
    for (int g = 0; g < 16; g++) { a0[g]=0.f; a1[g]=0.f; }
    const float* w1a = w1 + t*128;
    const float* w1b = w1 + (t+128)*128;
    const float4* S4 = (const float4*)Ssh;
    #pragma unroll 2
    for (int d = 0; d < 128; d++) {
        float wa = w1a[d], wb = w1b[d];
        #pragma unroll
        for (int q = 0; q < 4; q++) {
            float4 sv = S4[d*4 + q];
            a0[q*4+0] += wa*sv.x; a0[q*4+1] += wa*sv.y; a0[q*4+2] += wa*sv.z; a0[q*4+3] += wa*sv.w;
            a1[q*4+0] += wb*sv.x; a1[q*4+1] += wb*sv.y; a1[q*4+2] += wb*sv.z; a1[q*4+3] += wb*sv.w;
        }
    }
    float bb0 = b1[t], bb1 = b1[t+128];
    #pragma unroll
    for (int g = 0; g < 16; g++) {
        float h0 = a0[g] + bb0;
        float h1 = a1[g] + bb1;
        h0 = 0.5f*h0*(1.f + erff(h0*0.70710678118654752f));   // exact GELU
        h1 = 0.5f*h1*(1.f + erff(h1*0.70710678118654752f));
        Hsh[t*20 + g]       = h0;
        Hsh[(t+128)*20 + g] = h1;
    }
    __syncthreads();
    // fc2: thread computes row dd = t
    float acc[16];
    #pragma unroll
    for (int g = 0; g < 16; g++) acc[g] = 0.f;
    const float* w2r = w2 + t*256;
    const float4* H4 = (const float4*)Hsh;
    #pragma unroll 2
    for (int h = 0; h < 256; h++) {
        float w = w2r[h];
        #pragma unroll
        for (int q = 0; q < 4; q++) {
            float4 hv = H4[h*5 + q];
            acc[q*4+0] += w*hv.x; acc[q*4+1] += w*hv.y; acc[q*4+2] += w*hv.z; acc[q*4+3] += w*hv.w;
        }
    }
    float bo = b2[t];
    size_t obase = (size_t)(b*ND + t)*NG + g0;
    #pragma unroll
    for (int g = 0; g < 16; g++)
        out[obase + g] = x[obase + g] + acc[g] + bo;
}

// ----------------------------------------------------------------
extern "C" void kernel_launch(void* const* d_in, const int* in_sizes, int n_in,
                              void* d_out, int out_size) {
    const float* x     = (const float*)d_in[0];
    const float* Phi   = (const float*)d_in[1];
    const float* Theta = (const float*)d_in[2];
    const float* gam   = (const float*)d_in[3];
    const float* bet   = (const float*)d_in[4];
    const float* w1    = (const float*)d_in[5];
    const float* b1    = (const float*)d_in[6];
    const float* w2    = (const float*)d_in[7];
    const float* b2    = (const float*)d_in[8];
    float* out = (float*)d_out;

    k_lnstats<<<64, 256>>>(x);
    k_build_M<<<dim3(64, 65), 256>>>(Phi, Theta);      // independent of LN/FFT
    k_fft_fwd<<<512, 256>>>(x, gam, bet);
    k_sf<<<NGF, 256>>>();
    k_ifft<<<512, 256>>>();
    k_mlp<<<dim3(NG/16, NB), 128>>>(x, w1, b1, w2, b2, out);
}

// round 2
// speedup vs baseline: 1.2861x; 1.2861x over previous
#include <cuda_runtime.h>
#include <math.h>

#define NB 8
#define ND 128
#define NG 2048
#define NL 24
#define NGF 1025
#define NDD 16384   // D*D

// swizzled smem index: kills bit-reversal bank conflicts, keeps butterflies conflict-free
#define IX(i) ((i) + ((i) >> 5))

// Scratch (device globals: allocation-free contract)
__device__ float  g_mean[NB*NG];
__device__ float  g_rstd[NB*NG];
__device__ float2 g_Xf[NGF*NB*ND];     // [f][b*128+d]  8.4 MB
__device__ float  g_M [(size_t)NGF*NDD];       // [f][h][d]     67.1 MB
__device__ float2 g_Sf[NB*ND*NGF];     // [b*128+h][f]  8.4 MB
__device__ float  g_S [NB*ND*NG];      // [b*128+h][g]  8.4 MB

// ---------------------------------------------------------------- LN stats
__global__ void k_lnstats(const float* __restrict__ x) {
    int id = blockIdx.x*256 + threadIdx.x;     // 0..16383 = (b,g)
    int b = id >> 11, g = id & 2047;
    const float* p = x + (size_t)b*ND*NG + g;
    float s = 0.f, ss = 0.f;
    #pragma unroll 8
    for (int d = 0; d < ND; d++) { float v = p[d*NG]; s += v; ss += v*v; }
    float mean = s * (1.f/ND);
    float var  = ss * (1.f/ND) - mean*mean;
    g_mean[id] = mean;
    g_rstd[id] = rsqrtf(var + 1e-5f);
}

// ---------------------------------------------------------------- radix-4 fused FFT 2048 (512 threads)
// DIT, bit-reversed input order. Stage1 (radix-2) + 5 fused radix-4 steps.
__device__ __forceinline__ void fft2048_r4(float* re, float* im, const float2* tw, int inv) {
    int t = threadIdx.x;   // 512
    __syncthreads();
    // stage 1: half=1, twiddle=1
    #pragma unroll
    for (int j = 0; j < 2; j++) {
        int k = t + j*512;            // butterfly 0..1023
        int i0 = IX(2*k), i1 = IX(2*k+1);
        float ar = re[i0], ai = im[i0], br = re[i1], bi = im[i1];
        re[i0] = ar+br; im[i0] = ai+bi;
        re[i1] = ar-br; im[i1] = ai-bi;
    }
    // fused radix-4 steps: q = 2, 8, 32, 128, 512
    #pragma unroll
    for (int s = 0; s < 5; s++) {
        int lq = 2*s + 1;
        int q  = 1 << lq;
        __syncthreads();
        int pos = t & (q-1);
        int i0l = ((t >> lq) << (lq+2)) + pos;
        int i0 = IX(i0l), i1 = IX(i0l+q), i2 = IX(i0l+2*q), i3 = IX(i0l+3*q);
        float2 w1 = tw[pos << (10-lq)];
        float2 w2 = tw[pos << (9-lq)];
        if (inv) { w1.y = -w1.y; w2.y = -w2.y; }
        float w3x = inv ? -w2.y : w2.y;     // t3 = -i*w2 (fwd) / +i*conj(w2) (inv)
        float w3y = inv ?  w2.x : -w2.x;
        float x0r=re[i0], x0i=im[i0];
        float x1r=re[i1], x1i=im[i1];
        float x2r=re[i2], x2i=im[i2];
        float x3r=re[i3], x3i=im[i3];
        float a1r = w1.x*x1r - w1.y*x1i, a1i = w1.x*x1i + w1.y*x1r;
        float a3r = w1.x*x3r - w1.y*x3i, a3i = w1.x*x3i + w1.y*x3r;
        float u0r = x0r+a1r, u0i = x0i+a1i;
        float u1r = x0r-a1r, u1i = x0i-a1i;
        float u2r = x2r+a3r, u2i = x2i+a3i;
        float u3r = x2r-a3r, u3i = x2i-a3i;
        float b2r = w2.x*u2r - w2.y*u2i, b2i = w2.x*u2i + w2.y*u2r;
        float b3r = w3x*u3r - w3y*u3i,  b3i = w3x*u3i + w3y*u3r;
        re[i0]=u0r+b2r; im[i0]=u0i+b2i;
        re[i2]=u0r-b2r; im[i2]=u0i-b2i;
        re[i1]=u1r+b3r; im[i1]=u1i+b3i;
        re[i3]=u1r-b3r; im[i3]=u1i-b3i;
    }
    __syncthreads();
}

// ---------------------------------------------------------------- forward: LN-apply + packed real FFT (2 rows/block)
__global__ void k_fft_fwd(const float* __restrict__ x,
                          const float* __restrict__ gamma,
                          const float* __restrict__ beta) {
    __shared__ float re[2112], im[2112];
    __shared__ float2 tw[1024];
    int t = threadIdx.x;   // 512
    int row0 = blockIdx.x*2, row1 = row0 + 1;
    int b = row0 >> 7;
    int d0 = row0 & 127, d1 = d0 + 1;
    for (int j = t; j < 1024; j += 512) {
        float sv, cv;
        sincosf(-6.2831853071795864769f * (float)j * (1.f/2048.f), &sv, &cv);
        tw[j] = make_float2(cv, sv);
    }
    const float* xp0 = x + (size_t)row0*NG;
    const float* xp1 = x + (size_t)row1*NG;
    const float* mp  = g_mean + b*NG;
    const float* rp  = g_rstd + b*NG;
    float ga0 = gamma[d0], be0 = beta[d0], ga1 = gamma[d1], be1 = beta[d1];
    #pragma unroll
    for (int j = 0; j < 4; j++) {
        int i = t + j*512;
        float m = mp[i], r = rp[i];
        float z0 = (xp0[i]-m)*r*ga0 + be0;
        float z1 = (xp1[i]-m)*r*ga1 + be1;
        int rv = __brev(i) >> 21;
        re[IX(rv)] = z0; im[IX(rv)] = z1;            // z0 + i*z1
    }
    fft2048_r4(re, im, tw, 0);
    // unpack two real spectra from one complex FFT
    for (int k = t; k <= 1024; k += 512) {
        int km = (2048 - k) & 2047;
        float zr = re[IX(k)],  zi = im[IX(k)];
        float mr = re[IX(km)], mi = im[IX(km)];
        float2 A  = make_float2(0.5f*(zr+mr), 0.5f*(zi-mi));
        float2 Bv = make_float2(0.5f*(zi+mi), 0.5f*(mr-zr));
        g_Xf[k*(NB*ND) + row0] = A;
        g_Xf[k*(NB*ND) + row1] = Bv;
    }
}

// ---------------------------------------------------------------- M[f,h,d] = sum_l Phi[l,f]*Theta[l,h,d]   (32 f per block)
__global__ void k_build_M(const float* __restrict__ Phi, const float* __restrict__ Theta) {
    __shared__ float sphi[NL*32];
    int t  = threadIdx.x;
    int i  = blockIdx.x*256 + t;      // h*128+d
    int f0 = blockIdx.y*32;
    for (int idx = t; idx < NL*32; idx += 256) {
        int l = idx >> 5, ff = idx & 31;
        sphi[idx] = (f0+ff < NGF) ? Phi[l*NGF + f0 + ff] : 0.f;
    }
    __syncthreads();
    float th[NL];
    #pragma unroll
    for (int l = 0; l < NL; l++) th[l] = Theta[l*NDD + i];
    float4 acc[8];
    #pragma unroll
    for (int j = 0; j < 8; j++) acc[j] = make_float4(0.f,0.f,0.f,0.f);
    #pragma unroll
    for (int l = 0; l < NL; l++) {
        const float4* sp = (const float4*)(sphi + l*32);
        float tl = th[l];
        #pragma unroll
        for (int j = 0; j < 8; j++) {
            float4 p = sp[j];
            acc[j].x += p.x*tl; acc[j].y += p.y*tl;
            acc[j].z += p.z*tl; acc[j].w += p.w*tl;
        }
    }
    #pragma unroll
    for (int j = 0; j < 8; j++) {
        float v[4] = {acc[j].x, acc[j].y, acc[j].z, acc[j].w};
        #pragma unroll
        for (int c = 0; c < 4; c++) {
            int ff = f0 + j*4 + c;
            if (ff < NGF) g_M[(size_t)ff*NDD + i] = v[c];
        }
    }
}

// ---------------------------------------------------------------- S_f[b,h,f] = sum_d M[f,h,d]*Xf[b,d,f]
// 256 threads: thread = (b = t&7, hq = t>>3), computes 4 h. M streamed from global
// (warp-broadcast dedup -> 64KB/block), X in padded smem (conflict-free float4).
__global__ void k_sf() {
    __shared__ float sXr[8*132], sXi[8*132];   // [b][d], pad 4
    int t = threadIdx.x;       // 256
    int f = blockIdx.x;
    for (int idx = t; idx < 1024; idx += 256) {
        float2 v = g_Xf[f*1024 + idx];
        int bb = idx >> 7, dd = idx & 127;
        sXr[bb*132 + dd] = v.x;
        sXi[bb*132 + dd] = v.y;
    }
    __syncthreads();
    int b = t & 7, hq = t >> 3;                // hq 0..31
    const float4* M4  = (const float4*)(g_M + (size_t)f*NDD);
    const float4* xr4 = (const float4*)sXr;
    const float4* xi4 = (const float4*)sXi;
    float accr[4] = {0.f,0.f,0.f,0.f};
    float acci[4] = {0.f,0.f,0.f,0.f};
    #pragma unroll
    for (int d4 = 0; d4 < 32; d4++) {
        float4 xr = xr4[b*33 + d4];
        float4 xi = xi4[b*33 + d4];
        #pragma unroll
        for (int j = 0; j < 4; j++) {
            float4 m = M4[(hq*4 + j)*32 + d4];
            accr[j] += m.x*xr.x + m.y*xr.y + m.z*xr.z + m.w*xr.w;
            acci[j] += m.x*xi.x + m.y*xi.y + m.z*xi.z + m.w*xi.w;
        }
    }
    #pragma unroll
    for (int j = 0; j < 4; j++) {
        int h = hq*4 + j;
        g_Sf[(size_t)(b*ND + h)*NGF + f] = make_float2(accr[j], acci[j]);
    }
}

// ---------------------------------------------------------------- packed irfft: ifft(S1 + i*S2) -> two real rows
__global__ void k_ifft() {
    __shared__ float re[2112], im[2112];
    __shared__ float2 tw[1024];
    int t = threadIdx.x;   // 512
    int row0 = blockIdx.x*2, row1 = row0 + 1;
    for (int j = t; j < 1024; j += 512) {
        float sv, cv;
        sincosf(-6.2831853071795864769f * (float)j * (1.f/2048.f), &sv, &cv);
        tw[j] = make_float2(cv, sv);
    }
    const float2* p0 = g_Sf + (size_t)row0*NGF;
    const float2* p1 = g_Sf + (size_t)row1*NGF;
    #pragma unroll
    for (int j = 0; j < 4; j++) {
        int i = t + j*512;
        int src = (i <= 1024) ? i : 2048 - i;
        float2 v0 = p0[src], v1 = p1[src];
        if (i > 1024) { v0.y = -v0.y; v1.y = -v1.y; }   // Hermitian mirror
        int rv = __brev(i) >> 21;
        re[IX(rv)] = v0.x - v1.y;      // Z = S1 + i*S2
        im[IX(rv)] = v0.y + v1.x;
    }
    fft2048_r4(re, im, tw, 1);
    const float sc = 1.0f/2048.0f;
    #pragma unroll
    for (int j = 0; j < 4; j++) {
        int i = t + j*512;
        g_S[(size_t)row0*NG + i] = re[IX(i)]*sc;
        g_S[(size_t)row1*NG + i] = im[IX(i)]*sc;
    }
}

// ---------------------------------------------------------------- fused MLP + residual (g-tile 16, 128 threads)
__global__ void k_mlp(const float* __restrict__ x,
                      const float* __restrict__ w1, const float* __restrict__ b1,
                      const float* __restrict__ w2, const float* __restrict__ b2,
                      float* __restrict__ out) {
    __shared__ float Ssh[128*16];
    __shared__ float Hsh[256*20];   // stride 20 floats (16B-aligned rows)
    int t  = threadIdx.x;           // 128
    int b  = blockIdx.y;
    int g0 = blockIdx.x * 16;
    for (int idx = t; idx < 128*16; idx += 128) {
        int d = idx >> 4, g = idx & 15;
        Ssh[idx] = g_S[(size_t)(b*ND + d)*NG + g0 + g];
    }
    __syncthreads();
    // fc1: thread computes rows t and t+128
    float a0[16], a1[16];
    #pragma unroll
    for (int g = 0; g < 16; g++) { a0[g]=0.f; a1[g]=0.f; }
    const float4* w1a = (const float4*)(w1 + t*128);
    const float4* w1b = (const float4*)(w1 + (t+128)*128);
    const float4* S4 = (const float4*)Ssh;
    #pragma unroll 4
    for (int d4 = 0; d4 < 32; d4++) {
        float4 wa4 = w1a[d4];
        float4 wb4 = w1b[d4];
        float wa_[4] = {wa4.x, wa4.y, wa4.z, wa4.w};
        float wb_[4] = {wb4.x, wb4.y, wb4.z, wb4.w};
        #pragma unroll
        for (int u = 0; u < 4; u++) {
            float wa = wa_[u], wb = wb_[u];
            int d = d4*4 + u;
            #pragma unroll
            for (int q = 0; q < 4; q++) {
                float4 sv = S4[d*4 + q];
                a0[q*4+0] += wa*sv.x; a0[q*4+1] += wa*sv.y; a0[q*4+2] += wa*sv.z; a0[q*4+3] += wa*sv.w;
                a1[q*4+0] += wb*sv.x; a1[q*4+1] += wb*sv.y; a1[q*4+2] += wb*sv.z; a1[q*4+3] += wb*sv.w;
            }
        }
    }
    float bb0 = b1[t], bb1 = b1[t+128];
    #pragma unroll
    for (int g = 0; g < 16; g++) {
        float h0 = a0[g] + bb0;
        float h1 = a1[g] + bb1;
        h0 = 0.5f*h0*(1.f + erff(h0*0.70710678118654752f));   // exact GELU
        h1 = 0.5f*h1*(1.f + erff(h1*0.70710678118654752f));
        Hsh[t*20 + g]       = h0;
        Hsh[(t+128)*20 + g] = h1;
    }
    __syncthreads();
    // fc2: thread computes row d = t
    float acc[16];
    #pragma unroll
    for (int g = 0; g < 16; g++) acc[g] = 0.f;
    const float4* w2r = (const float4*)(w2 + t*256);
    const float4* H4 = (const float4*)Hsh;
    #pragma unroll 4
    for (int h4 = 0; h4 < 64; h4++) {
        float4 wv4 = w2r[h4];
        float wv_[4] = {wv4.x, wv4.y, wv4.z, wv4.w};
        #pragma unroll
        for (int u = 0; u < 4; u++) {
            float w = wv_[u];
            int h = h4*4 + u;
            #pragma unroll
            for (int q = 0; q < 4; q++) {
                float4 hv = H4[h*5 + q];
                acc[q*4+0] += w*hv.x; acc[q*4+1] += w*hv.y; acc[q*4+2] += w*hv.z; acc[q*4+3] += w*hv.w;
            }
        }
    }
    float bo = b2[t];
    size_t obase = (size_t)(b*ND + t)*NG + g0;
    #pragma unroll
    for (int g = 0; g < 16; g++)
        out[obase + g] = x[obase + g] + acc[g] + bo;
}

// ----------------------------------------------------------------
extern "C" void kernel_launch(void* const* d_in, const int* in_sizes, int n_in,
                              void* d_out, int out_size) {
    const float* x     = (const float*)d_in[0];
    const float* Phi   = (const float*)d_in[1];
    const float* Theta = (const float*)d_in[2];
    const float* gam   = (const float*)d_in[3];
    const float* bet   = (const float*)d_in[4];
    const float* w1    = (const float*)d_in[5];
    const float* b1    = (const float*)d_in[6];
    const float* w2    = (const float*)d_in[7];
    const float* b2    = (const float*)d_in[8];
    float* out = (float*)d_out;

    k_lnstats<<<64, 256>>>(x);
    k_build_M<<<dim3(64, 33), 256>>>(Phi, Theta);
    k_fft_fwd<<<512, 512>>>(x, gam, bet);
    k_sf<<<NGF, 256>>>();
    k_ifft<<<512, 512>>>();
    k_mlp<<<dim3(NG/16, NB), 128>>>(x, w1, b1, w2, b2, out);
}

// round 5
// speedup vs baseline: 3.1749x; 2.4687x over previous
#include <cuda_runtime.h>
#include <math.h>

#define NB 8
#define ND 128
#define NG 2048
#define NL 24
#define NGF 1025
#define NDD 16384   // D*D

// swizzled smem index for FFT: kills bit-reversal bank conflicts
#define IX(i) ((i) + ((i) >> 5))

// Scratch (device globals: allocation-free contract)
__device__ float  g_mean[NB*NG];
__device__ float  g_rstd[NB*NG];
__device__ float2 g_Xf[NGF*NB*ND];            // [f][b*128+d]
__device__ float  g_M [(size_t)NGF*NDD];      // [f][h][d]  67.1 MB
__device__ float2 g_Sf[NB*ND*NGF];            // [b*128+h][f]
__device__ float  g_S [NB*ND*NG];             // [b*128+h][g]

// ---------------------------------------------------------------- tf32 helpers
__device__ __forceinline__ unsigned tf32(float v) {
    unsigned u; asm("cvt.rna.tf32.f32 %0, %1;" : "=r"(u) : "f"(v)); return u;
}
__device__ __forceinline__ void mma8(float* c, const unsigned* a, const unsigned* b) {
    asm volatile("mma.sync.aligned.m16n8k8.row.col.f32.tf32.tf32.f32 "
        "{%0,%1,%2,%3},{%4,%5,%6,%7},{%8,%9},{%0,%1,%2,%3};"
        : "+f"(c[0]), "+f"(c[1]), "+f"(c[2]), "+f"(c[3])
        : "r"(a[0]), "r"(a[1]), "r"(a[2]), "r"(a[3]), "r"(b[0]), "r"(b[1]));
}
__device__ __forceinline__ float gelu_exact(float v) {
    return 0.5f*v*(1.f + erff(v*0.70710678118654752f));
}

// ---------------------------------------------------------------- LN stats (4-way d split)
__global__ void k_lnstats(const float* __restrict__ x) {
    __shared__ float ps[4*128], pss[4*128];
    int t = threadIdx.x;               // 512
    int g = t & 127, dq = t >> 7;      // dq 0..3
    int b = blockIdx.y;
    int g0 = blockIdx.x * 128;
    const float* p = x + (size_t)b*ND*NG + (size_t)(dq*32)*NG + g0 + g;
    float s = 0.f, ss = 0.f;
    #pragma unroll 8
    for (int d = 0; d < 32; d++) { float v = p[(size_t)d*NG]; s += v; ss += v*v; }
    ps[dq*128+g] = s; pss[dq*128+g] = ss;
    __syncthreads();
    if (dq == 0) {
        float S  = ps[g]  + ps[128+g]  + ps[256+g]  + ps[384+g];
        float SS = pss[g] + pss[128+g] + pss[256+g] + pss[384+g];
        float mean = S * (1.f/ND);
        float var  = SS * (1.f/ND) - mean*mean;
        g_mean[b*NG + g0 + g] = mean;
        g_rstd[b*NG + g0 + g] = rsqrtf(var + 1e-5f);
    }
}

// ---------------------------------------------------------------- radix-4 fused FFT 2048 (512 threads)
__device__ __forceinline__ void fft2048_r4(float* re, float* im, const float2* tw, int inv) {
    int t = threadIdx.x;   // 512
    __syncthreads();
    #pragma unroll
    for (int j = 0; j < 2; j++) {
        int k = t + j*512;
        int i0 = IX(2*k), i1 = IX(2*k+1);
        float ar = re[i0], ai = im[i0], br = re[i1], bi = im[i1];
        re[i0] = ar+br; im[i0] = ai+bi;
        re[i1] = ar-br; im[i1] = ai-bi;
    }
    #pragma unroll
    for (int s = 0; s < 5; s++) {
        int lq = 2*s + 1;
        int q  = 1 << lq;
        __syncthreads();
        int pos = t & (q-1);
        int i0l = ((t >> lq) << (lq+2)) + pos;
        int i0 = IX(i0l), i1 = IX(i0l+q), i2 = IX(i0l+2*q), i3 = IX(i0l+3*q);
        float2 w1 = tw[pos << (10-lq)];
        float2 w2 = tw[pos << (9-lq)];
        if (inv) { w1.y = -w1.y; w2.y = -w2.y; }
        float w3x = inv ? -w2.y : w2.y;
        float w3y = inv ?  w2.x : -w2.x;
        float x0r=re[i0], x0i=im[i0];
        float x1r=re[i1], x1i=im[i1];
        float x2r=re[i2], x2i=im[i2];
        float x3r=re[i3], x3i=im[i3];
        float a1r = w1.x*x1r - w1.y*x1i, a1i = w1.x*x1i + w1.y*x1r;
        float a3r = w1.x*x3r - w1.y*x3i, a3i = w1.x*x3i + w1.y*x3r;
        float u0r = x0r+a1r, u0i = x0i+a1i;
        float u1r = x0r-a1r, u1i = x0i-a1i;
        float u2r = x2r+a3r, u2i = x2i+a3i;
        float u3r = x2r-a3r, u3i = x2i-a3i;
        float b2r = w2.x*u2r - w2.y*u2i, b2i = w2.x*u2i + w2.y*u2r;
        float b3r = w3x*u3r - w3y*u3i,  b3i = w3x*u3i + w3y*u3r;
        re[i0]=u0r+b2r; im[i0]=u0i+b2i;
        re[i2]=u0r-b2r; im[i2]=u0i-b2i;
        re[i1]=u1r+b3r; im[i1]=u1i+b3i;
        re[i3]=u1r-b3r; im[i3]=u1i-b3i;
    }
    __syncthreads();
}

// ---------------------------------------------------------------- LN-apply + packed real FFT
__global__ void k_fft_fwd(const float* __restrict__ x,
                          const float* __restrict__ gamma,
                          const float* __restrict__ beta) {
    __shared__ float re[2112], im[2112];
    __shared__ float2 tw[1024];
    int t = threadIdx.x;   // 512
    int row0 = blockIdx.x*2, row1 = row0 + 1;
    int b = row0 >> 7;
    int d0 = row0 & 127, d1 = d0 + 1;
    for (int j = t; j < 1024; j += 512) {
        float sv, cv;
        sincosf(-6.2831853071795864769f * (float)j * (1.f/2048.f), &sv, &cv);
        tw[j] = make_float2(cv, sv);
    }
    const float* xp0 = x + (size_t)row0*NG;
    const float* xp1 = x + (size_t)row1*NG;
    const float* mp  = g_mean + b*NG;
    const float* rp  = g_rstd + b*NG;
    float ga0 = gamma[d0], be0 = beta[d0], ga1 = gamma[d1], be1 = beta[d1];
    #pragma unroll
    for (int j = 0; j < 4; j++) {
        int i = t + j*512;
        float m = mp[i], r = rp[i];
        float z0 = (xp0[i]-m)*r*ga0 + be0;
        float z1 = (xp1[i]-m)*r*ga1 + be1;
        int rv = __brev(i) >> 21;
        re[IX(rv)] = z0; im[IX(rv)] = z1;
    }
    fft2048_r4(re, im, tw, 0);
    for (int k = t; k <= 1024; k += 512) {
        int km = (2048 - k) & 2047;
        float zr = re[IX(k)],  zi = im[IX(k)];
        float mr = re[IX(km)], mi = im[IX(km)];
        float2 A  = make_float2(0.5f*(zr+mr), 0.5f*(zi-mi));
        float2 Bv = make_float2(0.5f*(zi+mi), 0.5f*(mr-zr));
        g_Xf[k*(NB*ND) + row0] = A;
        g_Xf[k*(NB*ND) + row1] = Bv;
    }
}

// ---------------------------------------------------------------- M[f,h,d] = sum_l Phi[l,f]*Theta[l,h,d]
__global__ void k_build_M(const float* __restrict__ Phi, const float* __restrict__ Theta) {
    __shared__ float sphi[NL*32];
    int t  = threadIdx.x;
    int i  = blockIdx.x*256 + t;      // h*128+d
    int f0 = blockIdx.y*32;
    for (int idx = t; idx < NL*32; idx += 256) {
        int l = idx >> 5, ff = idx & 31;
        sphi[idx] = (f0+ff < NGF) ? Phi[l*NGF + f0 + ff] : 0.f;
    }
    __syncthreads();
    float th[NL];
    #pragma unroll
    for (int l = 0; l < NL; l++) th[l] = Theta[l*NDD + i];
    float4 acc[8];
    #pragma unroll
    for (int j = 0; j < 8; j++) acc[j] = make_float4(0.f,0.f,0.f,0.f);
    #pragma unroll
    for (int l = 0; l < NL; l++) {
        const float4* sp = (const float4*)(sphi + l*32);
        float tl = th[l];
        #pragma unroll
        for (int j = 0; j < 8; j++) {
            float4 p = sp[j];
            acc[j].x += p.x*tl; acc[j].y += p.y*tl;
            acc[j].z += p.z*tl; acc[j].w += p.w*tl;
        }
    }
    #pragma unroll
    for (int j = 0; j < 8; j++) {
        float v[4] = {acc[j].x, acc[j].y, acc[j].z, acc[j].w};
        #pragma unroll
        for (int c = 0; c < 4; c++) {
            int ff = f0 + j*4 + c;
            if (ff < NGF) g_M[(size_t)ff*NDD + i] = v[c];
        }
    }
}

// ---------------------------------------------------------------- S_f[b,h,f] = sum_d M[f,h,d]*Xf[b,d,f]
// software-pipelined: double-buffered M prefetch to keep >=8 LDG.128 in flight
__global__ void __launch_bounds__(256) k_sf() {
    __shared__ float sXr[8*132], sXi[8*132];
    int t = threadIdx.x;       // 256
    int f = blockIdx.x;
    for (int idx = t; idx < 1024; idx += 256) {
        float2 v = g_Xf[f*1024 + idx];
        int bb = idx >> 7, dd = idx & 127;
        sXr[bb*132 + dd] = v.x;
        sXi[bb*132 + dd] = v.y;
    }
    __syncthreads();
    int b = t & 7, hq = t >> 3;                // hq 0..31
    const float4* M4  = (const float4*)(g_M + (size_t)f*NDD) + hq*128;  // 4 rows of 32 float4
    const float4* xr4 = (const float4*)sXr + b*33;
    const float4* xi4 = (const float4*)sXi + b*33;
    float4 m[4], n[4];
    #pragma unroll
    for (int j = 0; j < 4; j++) m[j] = M4[j*32];
    float accr[4] = {0.f,0.f,0.f,0.f};
    float acci[4] = {0.f,0.f,0.f,0.f};
    #pragma unroll 4
    for (int d4 = 0; d4 < 31; d4++) {
        #pragma unroll
        for (int j = 0; j < 4; j++) n[j] = M4[j*32 + d4 + 1];
        float4 xr = xr4[d4], xi = xi4[d4];
        #pragma unroll
        for (int j = 0; j < 4; j++) {
            accr[j] += m[j].x*xr.x + m[j].y*xr.y + m[j].z*xr.z + m[j].w*xr.w;
            acci[j] += m[j].x*xi.x + m[j].y*xi.y + m[j].z*xi.z + m[j].w*xi.w;
        }
        #pragma unroll
        for (int j = 0; j < 4; j++) m[j] = n[j];
    }
    {
        float4 xr = xr4[31], xi = xi4[31];
        #pragma unroll
        for (int j = 0; j < 4; j++) {
            accr[j] += m[j].x*xr.x + m[j].y*xr.y + m[j].z*xr.z + m[j].w*xr.w;
            acci[j] += m[j].x*xi.x + m[j].y*xi.y + m[j].z*xi.z + m[j].w*xi.w;
        }
    }
    #pragma unroll
    for (int j = 0; j < 4; j++) {
        int h = hq*4 + j;
        g_Sf[(size_t)(b*ND + h)*NGF + f] = make_float2(accr[j], acci[j]);
    }
}

// ---------------------------------------------------------------- packed irfft
__global__ void k_ifft() {
    __shared__ float re[2112], im[2112];
    __shared__ float2 tw[1024];
    int t = threadIdx.x;   // 512
    int row0 = blockIdx.x*2, row1 = row0 + 1;
    for (int j = t; j < 1024; j += 512) {
        float sv, cv;
        sincosf(-6.2831853071795864769f * (float)j * (1.f/2048.f), &sv, &cv);
        tw[j] = make_float2(cv, sv);
    }
    const float2* p0 = g_Sf + (size_t)row0*NGF;
    const float2* p1 = g_Sf + (size_t)row1*NGF;
    #pragma unroll
    for (int j = 0; j < 4; j++) {
        int i = t + j*512;
        int src = (i <= 1024) ? i : 2048 - i;
        float2 v0 = p0[src], v1 = p1[src];
        if (i > 1024) { v0.y = -v0.y; v1.y = -v1.y; }
        int rv = __brev(i) >> 21;
        re[IX(rv)] = v0.x - v1.y;
        im[IX(rv)] = v0.y + v1.x;
    }
    fft2048_r4(re, im, tw, 1);
    const float sc = 1.0f/2048.0f;
    #pragma unroll
    for (int j = 0; j < 4; j++) {
        int i = t + j*512;
        g_S[(size_t)row0*NG + i] = re[IX(i)]*sc;
        g_S[(size_t)row1*NG + i] = im[IX(i)]*sc;
    }
}

// ---------------------------------------------------------------- tensor-core MLP (tf32 mma)
// Block: b fixed, 32-wide g tile. Computes Ht = S^T W1^T (gelu), outT = Ht W2^T.
// smem layout (floats): Ssm [32][132] @0 (later W2 chunk [128][20], then Osm [128][33])
//                       Hsm [32][268] @4224 (during fc1 k-loop: W1 chunk [256][20])
#define MLP_SMEM_BYTES (12800*4)
__global__ void __launch_bounds__(256) k_mlp_tc(
        const float* __restrict__ x,
        const float* __restrict__ w1, const float* __restrict__ b1,
        const float* __restrict__ w2, const float* __restrict__ b2,
        float* __restrict__ out) {
    extern __shared__ float buf[];
    float* Ssm = buf;          // [32][132]
    float* Hsm = buf + 4224;   // [32][268]
    float* W1sm = Hsm;         // alias during fc1 k-loop: [256][20]
    float* W2sm = Ssm;         // alias during fc2 k-loop: [128][20]
    float* Osm  = Ssm;         // alias at epilogue: [128][33]

    int t = threadIdx.x;           // 256
    int lane = t & 31, w = t >> 5; // 8 warps
    int gid = lane >> 2, tig = lane & 3;
    int b = blockIdx.y, g0 = blockIdx.x * 32;

    // ---- load S tile transposed into Ssm[g][d] as tf32 ----
    {
        int d = t & 127, gq = t >> 7;
        const float* src = g_S + ((size_t)(b*ND + d))*NG + g0 + gq*16;
        #pragma unroll
        for (int j = 0; j < 4; j++) {
            float4 v = *(const float4*)(src + j*4);
            int gg = gq*16 + j*4;
            Ssm[(gg+0)*132 + d] = __uint_as_float(tf32(v.x));
            Ssm[(gg+1)*132 + d] = __uint_as_float(tf32(v.y));
            Ssm[(gg+2)*132 + d] = __uint_as_float(tf32(v.z));
            Ssm[(gg+3)*132 + d] = __uint_as_float(tf32(v.w));
        }
    }

    // ---- fc1: Ht[32g][256h], warp w owns h in [w*32, w*32+32) ----
    float acc1[2][4][4];
    #pragma unroll
    for (int i = 0; i < 2; i++)
        #pragma unroll
        for (int jn = 0; jn < 4; jn++)
            #pragma unroll
            for (int c = 0; c < 4; c++) acc1[i][jn][c] = 0.f;
    int n0w = w * 32;
    for (int kc = 0; kc < 8; kc++) {       // K=128 in chunks of 16
        __syncthreads();
        #pragma unroll
        for (int r = 0; r < 4; r++) {      // stage W1[256][16] -> W1sm[256][20]
            int h  = r*64 + (t >> 2);
            int kk = (t & 3) * 4;
            float4 v = *(const float4*)(w1 + h*128 + kc*16 + kk);
            float4 c4;
            c4.x = __uint_as_float(tf32(v.x));
            c4.y = __uint_as_float(tf32(v.y));
            c4.z = __uint_as_float(tf32(v.z));
            c4.w = __uint_as_float(tf32(v.w));
            *(float4*)(W1sm + h*20 + kk) = c4;
        }
        __syncthreads();
        #pragma unroll
        for (int ks = 0; ks < 2; ks++) {
            int ka = kc*16 + ks*8 + tig;
            unsigned af[2][4];
            #pragma unroll
            for (int i = 0; i < 2; i++) {
                int r0 = i*16 + gid;
                af[i][0] = __float_as_uint(Ssm[r0*132 + ka]);
                af[i][1] = __float_as_uint(Ssm[(r0+8)*132 + ka]);
                af[i][2] = __float_as_uint(Ssm[r0*132 + ka + 4]);
                af[i][3] = __float_as_uint(Ssm[(r0+8)*132 + ka + 4]);
            }
            int kb = ks*8 + tig;
            #pragma unroll
            for (int jn = 0; jn < 4; jn++) {
                int n0 = n0w + jn*8;
                unsigned bf[2];
                bf[0] = __float_as_uint(W1sm[(n0+gid)*20 + kb]);
                bf[1] = __float_as_uint(W1sm[(n0+gid)*20 + kb + 4]);
                #pragma unroll
                for (int i = 0; i < 2; i++) mma8(acc1[i][jn], af[i], bf);
            }
        }
    }
    __syncthreads();   // done with W1sm region -> becomes Hsm
    // bias + GELU -> Hsm[g][h]
    #pragma unroll
    for (int jn = 0; jn < 4; jn++) {
        int n0 = n0w + jn*8;
        float bb0 = b1[n0 + 2*tig];
        float bb1 = b1[n0 + 2*tig + 1];
        #pragma unroll
        for (int i = 0; i < 2; i++) {
            int r0 = i*16 + gid;
            Hsm[r0*268     + n0 + 2*tig]     = gelu_exact(acc1[i][jn][0] + bb0);
            Hsm[r0*268     + n0 + 2*tig + 1] = gelu_exact(acc1[i][jn][1] + bb1);
            Hsm[(r0+8)*268 + n0 + 2*tig]     = gelu_exact(acc1[i][jn][2] + bb0);
            Hsm[(r0+8)*268 + n0 + 2*tig + 1] = gelu_exact(acc1[i][jn][3] + bb1);
        }
    }

    // ---- fc2: outT[32g][128d], warp w owns d in [w*16, w*16+16) ----
    float acc2[2][2][4];
    #pragma unroll
    for (int i = 0; i < 2; i++)
        #pragma unroll
        for (int jn = 0; jn < 2; jn++)
            #pragma unroll
            for (int c = 0; c < 4; c++) acc2[i][jn][c] = 0.f;
    int n0w2 = w * 16;
    for (int kc = 0; kc < 16; kc++) {      // K=256 in chunks of 16
        __syncthreads();
        #pragma unroll
        for (int r = 0; r < 2; r++) {      // stage W2[128][16] -> W2sm[128][20]
            int d  = r*64 + (t >> 2);
            int kk = (t & 3) * 4;
            float4 v = *(const float4*)(w2 + d*256 + kc*16 + kk);
            float4 c4;
            c4.x = __uint_as_float(tf32(v.x));
            c4.y = __uint_as_float(tf32(v.y));
            c4.z = __uint_as_float(tf32(v.z));
            c4.w = __uint_as_float(tf32(v.w));
            *(float4*)(W2sm + d*20 + kk) = c4;
        }
        __syncthreads();
        #pragma unroll
        for (int ks = 0; ks < 2; ks++) {
            int ka = kc*16 + ks*8 + tig;
            unsigned af[2][4];
            #pragma unroll
            for (int i = 0; i < 2; i++) {
                int r0 = i*16 + gid;
                af[i][0] = tf32(Hsm[r0*268 + ka]);
                af[i][1] = tf32(Hsm[(r0+8)*268 + ka]);
                af[i][2] = tf32(Hsm[r0*268 + ka + 4]);
                af[i][3] = tf32(Hsm[(r0+8)*268 + ka + 4]);
            }
            int kb = ks*8 + tig;
            #pragma unroll
            for (int jn = 0; jn < 2; jn++) {
                int n0 = n0w2 + jn*8;
                unsigned bf[2];
                bf[0] = __float_as_uint(W2sm[(n0+gid)*20 + kb]);
                bf[1] = __float_as_uint(W2sm[(n0+gid)*20 + kb + 4]);
                #pragma unroll
                for (int i = 0; i < 2; i++) mma8(acc2[i][jn], af[i], bf);
            }
        }
    }
    __syncthreads();   // done with W2sm region -> becomes Osm
    // transpose through Osm[d][g]
    #pragma unroll
    for (int jn = 0; jn < 2; jn++) {
        int n0 = n0w2 + jn*8;
        #pragma unroll
        for (int i = 0; i < 2; i++) {
            int r0 = i*16 + gid;
            Osm[(n0+2*tig)*33   + r0]   = acc2[i][jn][0];
            Osm[(n0+2*tig+1)*33 + r0]   = acc2[i][jn][1];
            Osm[(n0+2*tig)*33   + r0+8] = acc2[i][jn][2];
            Osm[(n0+2*tig+1)*33 + r0+8] = acc2[i][jn][3];
        }
    }
    __syncthreads();
    // final: out = x + outT^T + b2 (coalesced float4 along g)
    #pragma unroll
    for (int r = 0; r < 4; r++) {
        int d = r*32 + (t >> 3);
        int g = (t & 7) * 4;
        float bias = b2[d];
        size_t o = ((size_t)(b*ND + d))*NG + g0 + g;
        float4 xv = *(const float4*)(x + o);
        float4 res;
        res.x = xv.x + Osm[d*33 + g]     + bias;
        res.y = xv.y + Osm[d*33 + g + 1] + bias;
        res.z = xv.z + Osm[d*33 + g + 2] + bias;
        res.w = xv.w + Osm[d*33 + g + 3] + bias;
        *(float4*)(out + o) = res;
    }
}

// ----------------------------------------------------------------
extern "C" void kernel_launch(void* const* d_in, const int* in_sizes, int n_in,
                              void* d_out, int out_size) {
    const float* x     = (const float*)d_in[0];
    const float* Phi   = (const float*)d_in[1];
    const float* Theta = (const float*)d_in[2];
    const float* gam   = (const float*)d_in[3];
    const float* bet   = (const float*)d_in[4];
    const float* w1    = (const float*)d_in[5];
    const float* b1    = (const float*)d_in[6];
    const float* w2    = (const float*)d_in[7];
    const float* b2    = (const float*)d_in[8];
    float* out = (float*)d_out;

    cudaFuncSetAttribute(k_mlp_tc, cudaFuncAttributeMaxDynamicSharedMemorySize, MLP_SMEM_BYTES);

    k_lnstats<<<dim3(16, 8), 512>>>(x);
    k_build_M<<<dim3(64, 33), 256>>>(Phi, Theta);
    k_fft_fwd<<<512, 512>>>(x, gam, bet);
    k_sf<<<NGF, 256>>>();
    k_ifft<<<512, 512>>>();
    k_mlp_tc<<<dim3(NG/32, NB), 256, MLP_SMEM_BYTES>>>(x, w1, b1, w2, b2, out);
}

// round 7
// speedup vs baseline: 3.4966x; 1.1013x over previous
#include <cuda_runtime.h>
#include <cuda_fp16.h>
#include <math.h>

#define NB 8
#define ND 128
#define NG 2048
#define NL 24
#define NGF 1025
#define NDD 16384   // D*D

// swizzled smem index for FFT: kills bit-reversal bank conflicts
#define IX(i) ((i) + ((i) >> 5))

// Scratch (device globals: allocation-free contract)
__device__ float  g_mean[NB*NG];
__device__ float  g_rstd[NB*NG];
__device__ float2 g_Xf[NGF*NB*ND];            // [f][b*128+d]
__device__ __half g_Mh[(size_t)NGF*NDD];      // [f][h][d]  33.6 MB (fp16)
__device__ float2 g_Sf[NB*ND*NGF];            // [b*128+h][f]
__device__ float  g_S [NB*ND*NG];             // [b*128+h][g]

// ---------------------------------------------------------------- tf32 helpers
__device__ __forceinline__ unsigned tf32(float v) {
    unsigned u; asm("cvt.rna.tf32.f32 %0, %1;" : "=r"(u) : "f"(v)); return u;
}
__device__ __forceinline__ void mma8(float* c, const unsigned* a, const unsigned* b) {
    asm volatile("mma.sync.aligned.m16n8k8.row.col.f32.tf32.tf32.f32 "
        "{%0,%1,%2,%3},{%4,%5,%6,%7},{%8,%9},{%0,%1,%2,%3};"
        : "+f"(c[0]), "+f"(c[1]), "+f"(c[2]), "+f"(c[3])
        : "r"(a[0]), "r"(a[1]), "r"(a[2]), "r"(a[3]), "r"(b[0]), "r"(b[1]));
}
__device__ __forceinline__ float gelu_exact(float v) {
    return 0.5f*v*(1.f + erff(v*0.70710678118654752f));
}

// ---------------------------------------------------------------- LN stats (4-way d split)
__global__ void k_lnstats(const float* __restrict__ x) {
    __shared__ float ps[4*128], pss[4*128];
    int t = threadIdx.x;               // 512
    int g = t & 127, dq = t >> 7;      // dq 0..3
    int b = blockIdx.y;
    int g0 = blockIdx.x * 128;
    const float* p = x + (size_t)b*ND*NG + (size_t)(dq*32)*NG + g0 + g;
    float s = 0.f, ss = 0.f;
    #pragma unroll 8
    for (int d = 0; d < 32; d++) { float v = p[(size_t)d*NG]; s += v; ss += v*v; }
    ps[dq*128+g] = s; pss[dq*128+g] = ss;
    __syncthreads();
    if (dq == 0) {
        float S  = ps[g]  + ps[128+g]  + ps[256+g]  + ps[384+g];
        float SS = pss[g] + pss[128+g] + pss[256+g] + pss[384+g];
        float mean = S * (1.f/ND);
        float var  = SS * (1.f/ND) - mean*mean;
        g_mean[b*NG + g0 + g] = mean;
        g_rstd[b*NG + g0 + g] = rsqrtf(var + 1e-5f);
    }
}

// ---------------------------------------------------------------- radix-4 fused FFT 2048 (512 threads)
__device__ __forceinline__ void fft2048_r4(float* re, float* im, const float2* tw, int inv) {
    int t = threadIdx.x;   // 512
    __syncthreads();
    #pragma unroll
    for (int j = 0; j < 2; j++) {
        int k = t + j*512;
        int i0 = IX(2*k), i1 = IX(2*k+1);
        float ar = re[i0], ai = im[i0], br = re[i1], bi = im[i1];
        re[i0] = ar+br; im[i0] = ai+bi;
        re[i1] = ar-br; im[i1] = ai-bi;
    }
    #pragma unroll
    for (int s = 0; s < 5; s++) {
        int lq = 2*s + 1;
        int q  = 1 << lq;
        __syncthreads();
        int pos = t & (q-1);
        int i0l = ((t >> lq) << (lq+2)) + pos;
        int i0 = IX(i0l), i1 = IX(i0l+q), i2 = IX(i0l+2*q), i3 = IX(i0l+3*q);
        float2 w1 = tw[pos << (10-lq)];
        float2 w2 = tw[pos << (9-lq)];
        if (inv) { w1.y = -w1.y; w2.y = -w2.y; }
        float w3x = inv ? -w2.y : w2.y;
        float w3y = inv ?  w2.x : -w2.x;
        float x0r=re[i0], x0i=im[i0];
        float x1r=re[i1], x1i=im[i1];
        float x2r=re[i2], x2i=im[i2];
        float x3r=re[i3], x3i=im[i3];
        float a1r = w1.x*x1r - w1.y*x1i, a1i = w1.x*x1i + w1.y*x1r;
        float a3r = w1.x*x3r - w1.y*x3i, a3i = w1.x*x3i + w1.y*x3r;
        float u0r = x0r+a1r, u0i = x0i+a1i;
        float u1r = x0r-a1r, u1i = x0i-a1i;
        float u2r = x2r+a3r, u2i = x2i+a3i;
        float u3r = x2r-a3r, u3i = x2i-a3i;
        float b2r = w2.x*u2r - w2.y*u2i, b2i = w2.x*u2i + w2.y*u2r;
        float b3r = w3x*u3r - w3y*u3i,  b3i = w3x*u3i + w3y*u3r;
        re[i0]=u0r+b2r; im[i0]=u0i+b2i;
        re[i2]=u0r-b2r; im[i2]=u0i-b2i;
        re[i1]=u1r+b3r; im[i1]=u1i+b3i;
        re[i3]=u1r-b3r; im[i3]=u1i-b3i;
    }
    __syncthreads();
}

// ---------------------------------------------------------------- LN-apply + packed real FFT
__global__ void k_fft_fwd(const float* __restrict__ x,
                          const float* __restrict__ gamma,
                          const float* __restrict__ beta) {
    __shared__ float re[2112], im[2112];
    __shared__ float2 tw[1024];
    int t = threadIdx.x;   // 512
    int row0 = blockIdx.x*2, row1 = row0 + 1;
    int b = row0 >> 7;
    int d0 = row0 & 127, d1 = d0 + 1;
    for (int j = t; j < 1024; j += 512) {
        float sv, cv;
        sincosf(-6.2831853071795864769f * (float)j * (1.f/2048.f), &sv, &cv);
        tw[j] = make_float2(cv, sv);
    }
    const float* xp0 = x + (size_t)row0*NG;
    const float* xp1 = x + (size_t)row1*NG;
    const float* mp  = g_mean + b*NG;
    const float* rp  = g_rstd + b*NG;
    float ga0 = gamma[d0], be0 = beta[d0], ga1 = gamma[d1], be1 = beta[d1];
    #pragma unroll
    for (int j = 0; j < 4; j++) {
        int i = t + j*512;
        float m = mp[i], r = rp[i];
        float z0 = (xp0[i]-m)*r*ga0 + be0;
        float z1 = (xp1[i]-m)*r*ga1 + be1;
        int rv = __brev(i) >> 21;
        re[IX(rv)] = z0; im[IX(rv)] = z1;
    }
    fft2048_r4(re, im, tw, 0);
    for (int k = t; k <= 1024; k += 512) {
        int km = (2048 - k) & 2047;
        float zr = re[IX(k)],  zi = im[IX(k)];
        float mr = re[IX(km)], mi = im[IX(km)];
        float2 A  = make_float2(0.5f*(zr+mr), 0.5f*(zi-mi));
        float2 Bv = make_float2(0.5f*(zi+mi), 0.5f*(mr-zr));
        g_Xf[k*(NB*ND) + row0] = A;
        g_Xf[k*(NB*ND) + row1] = Bv;
    }
}

// ---------------------------------------------------------------- M[f,h,d] = sum_l Phi[l,f]*Theta[l,h,d]  (fp16 out)
__global__ void k_build_M(const float* __restrict__ Phi, const float* __restrict__ Theta) {
    __shared__ float sphi[NL*32];
    int t  = threadIdx.x;
    int i  = blockIdx.x*256 + t;      // h*128+d
    int f0 = blockIdx.y*32;
    for (int idx = t; idx < NL*32; idx += 256) {
        int l = idx >> 5, ff = idx & 31;
        sphi[idx] = (f0+ff < NGF) ? Phi[l*NGF + f0 + ff] : 0.f;
    }
    __syncthreads();
    float th[NL];
    #pragma unroll
    for (int l = 0; l < NL; l++) th[l] = Theta[l*NDD + i];
    float4 acc[8];
    #pragma unroll
    for (int j = 0; j < 8; j++) acc[j] = make_float4(0.f,0.f,0.f,0.f);
    #pragma unroll
    for (int l = 0; l < NL; l++) {
        const float4* sp = (const float4*)(sphi + l*32);
        float tl = th[l];
        #pragma unroll
        for (int j = 0; j < 8; j++) {
            float4 p = sp[j];
            acc[j].x += p.x*tl; acc[j].y += p.y*tl;
            acc[j].z += p.z*tl; acc[j].w += p.w*tl;
        }
    }
    #pragma unroll
    for (int j = 0; j < 8; j++) {
        float v[4] = {acc[j].x, acc[j].y, acc[j].z, acc[j].w};
        #pragma unroll
        for (int c = 0; c < 4; c++) {
            int ff = f0 + j*4 + c;
            if (ff < NGF) g_Mh[(size_t)ff*NDD + i] = __float2half_rn(v[c]);
        }
    }
}

// ---------------------------------------------------------------- S_f[b,h,f] = sum_d M[f,h,d]*Xf[b,d,f]
// fp16 M: uint4 = 8 halves per load; double-buffered prefetch
__global__ void __launch_bounds__(256) k_sf() {
    __shared__ float sXr[8*132], sXi[8*132];
    int t = threadIdx.x;       // 256
    int f = blockIdx.x;
    for (int idx = t; idx < 1024; idx += 256) {
        float2 v = g_Xf[f*1024 + idx];
        int bb = idx >> 7, dd = idx & 127;
        sXr[bb*132 + dd] = v.x;
        sXi[bb*132 + dd] = v.y;
    }
    __syncthreads();
    int b = t & 7, hq = t >> 3;                // hq 0..31
    // thread owns 4 consecutive h rows; each row = 128 halves = 16 uint4
    const uint4* M8 = (const uint4*)(g_Mh + (size_t)f*NDD) + hq*64;
    const float4* xr4 = (const float4*)sXr + b*33;
    const float4* xi4 = (const float4*)sXi + b*33;
    uint4 m[4], n[4];
    #pragma unroll
    for (int j = 0; j < 4; j++) m[j] = M8[j*16];
    float accr[4] = {0.f,0.f,0.f,0.f};
    float acci[4] = {0.f,0.f,0.f,0.f};
    #pragma unroll 4
    for (int d8 = 0; d8 < 15; d8++) {
        #pragma unroll
        for (int j = 0; j < 4; j++) n[j] = M8[j*16 + d8 + 1];
        float4 xr0 = xr4[d8*2], xr1 = xr4[d8*2+1];
        float4 xi0 = xi4[d8*2], xi1 = xi4[d8*2+1];
        #pragma unroll
        for (int j = 0; j < 4; j++) {
            float2 p0 = __half22float2(*(const __half2*)&m[j].x);
            float2 p1 = __half22float2(*(const __half2*)&m[j].y);
            float2 p2 = __half22float2(*(const __half2*)&m[j].z);
            float2 p3 = __half22float2(*(const __half2*)&m[j].w);
            accr[j] += p0.x*xr0.x + p0.y*xr0.y + p1.x*xr0.z + p1.y*xr0.w
                     + p2.x*xr1.x + p2.y*xr1.y + p3.x*xr1.z + p3.y*xr1.w;
            acci[j] += p0.x*xi0.x + p0.y*xi0.y + p1.x*xi0.z + p1.y*xi0.w
                     + p2.x*xi1.x + p2.y*xi1.y + p3.x*xi1.z + p3.y*xi1.w;
        }
        #pragma unroll
        for (int j = 0; j < 4; j++) m[j] = n[j];
    }
    {
        float4 xr0 = xr4[30], xr1 = xr4[31];
        float4 xi0 = xi4[30], xi1 = xi4[31];
        #pragma unroll
        for (int j = 0; j < 4; j++) {
            float2 p0 = __half22float2(*(const __half2*)&m[j].x);
            float2 p1 = __half22float2(*(const __half2*)&m[j].y);
            float2 p2 = __half22float2(*(const __half2*)&m[j].z);
            float2 p3 = __half22float2(*(const __half2*)&m[j].w);
            accr[j] += p0.x*xr0.x + p0.y*xr0.y + p1.x*xr0.z + p1.y*xr0.w
                     + p2.x*xr1.x + p2.y*xr1.y + p3.x*xr1.z + p3.y*xr1.w;
            acci[j] += p0.x*xi0.x + p0.y*xi0.y + p1.x*xi0.z + p1.y*xi0.w
                     + p2.x*xi1.x + p2.y*xi1.y + p3.x*xi1.z + p3.y*xi1.w;
        }
    }
    #pragma unroll
    for (int j = 0; j < 4; j++) {
        int h = hq*4 + j;
        g_Sf[(size_t)(b*ND + h)*NGF + f] = make_float2(accr[j], acci[j]);
    }
}

// ---------------------------------------------------------------- packed irfft
__global__ void k_ifft() {
    __shared__ float re[2112], im[2112];
    __shared__ float2 tw[1024];
    int t = threadIdx.x;   // 512
    int row0 = blockIdx.x*2, row1 = row0 + 1;
    for (int j = t; j < 1024; j += 512) {
        float sv, cv;
        sincosf(-6.2831853071795864769f * (float)j * (1.f/2048.f), &sv, &cv);
        tw[j] = make_float2(cv, sv);
    }
    const float2* p0 = g_Sf + (size_t)row0*NGF;
    const float2* p1 = g_Sf + (size_t)row1*NGF;
    #pragma unroll
    for (int j = 0; j < 4; j++) {
        int i = t + j*512;
        int src = (i <= 1024) ? i : 2048 - i;
        float2 v0 = p0[src], v1 = p1[src];
        if (i > 1024) { v0.y = -v0.y; v1.y = -v1.y; }
        int rv = __brev(i) >> 21;
        re[IX(rv)] = v0.x - v1.y;
        im[IX(rv)] = v0.y + v1.x;
    }
    fft2048_r4(re, im, tw, 1);
    const float sc = 1.0f/2048.0f;
    #pragma unroll
    for (int j = 0; j < 4; j++) {
        int i = t + j*512;
        g_S[(size_t)row0*NG + i] = re[IX(i)]*sc;
        g_S[(size_t)row1*NG + i] = im[IX(i)]*sc;
    }
}

// ---------------------------------------------------------------- tensor-core MLP (tf32 mma), g-tile 64
// smem floats: Ssm [64][132] @0 (aliases: W2 chunk [128][20], Osm [128][66])
//              Hsm [64][268] @8448 (alias during fc1 k-loop: W1 chunk [256][20])
#define MLP_SMEM_BYTES ((8448 + 17152)*4)
__global__ void __launch_bounds__(256) k_mlp_tc(
        const float* __restrict__ x,
        const float* __restrict__ w1, const float* __restrict__ b1,
        const float* __restrict__ w2, const float* __restrict__ b2,
        float* __restrict__ out) {
    extern __shared__ float buf[];
    float* Ssm = buf;          // [64][132]
    float* Hsm = buf + 8448;   // [64][268]
    float* W1sm = Hsm;         // alias during fc1 k-loop: [256][20]
    float* W2sm = Ssm;         // alias during fc2 k-loop: [128][20]
    float* Osm  = Ssm;         // alias at epilogue: [128][66]

    int t = threadIdx.x;           // 256
    int lane = t & 31, w = t >> 5; // 8 warps
    int gid = lane >> 2, tig = lane & 3;
    int b = blockIdx.y, g0 = blockIdx.x * 64;

    // ---- load S tile transposed into Ssm[g][d] as tf32 ----
    {
        int d = t & 127, gq = t >> 7;  // gq 0..1, each covers 32 g
        const float* src = g_S + ((size_t)(b*ND + d))*NG + g0 + gq*32;
        #pragma unroll
        for (int j = 0; j < 8; j++) {
            float4 v = *(const float4*)(src + j*4);
            int gg = gq*32 + j*4;
            Ssm[(gg+0)*132 + d] = __uint_as_float(tf32(v.x));
            Ssm[(gg+1)*132 + d] = __uint_as_float(tf32(v.y));
            Ssm[(gg+2)*132 + d] = __uint_as_float(tf32(v.z));
            Ssm[(gg+3)*132 + d] = __uint_as_float(tf32(v.w));
        }
    }

    // ---- fc1: Ht[64g][256h], warp w owns h in [w*32, w*32+32) ----
    float acc1[4][4][4];
    #pragma unroll
    for (int i = 0; i < 4; i++)
        #pragma unroll
        for (int jn = 0; jn < 4; jn++)
            #pragma unroll
            for (int c = 0; c < 4; c++) acc1[i][jn][c] = 0.f;
    int n0w = w * 32;
    for (int kc = 0; kc < 8; kc++) {       // K=128 in chunks of 16
        __syncthreads();
        #pragma unroll
        for (int r = 0; r < 4; r++) {      // stage W1[256][16] -> W1sm[256][20]
            int h  = r*64 + (t >> 2);
            int kk = (t & 3) * 4;
            float4 v = *(const float4*)(w1 + h*128 + kc*16 + kk);
            float4 c4;
            c4.x = __uint_as_float(tf32(v.x));
            c4.y = __uint_as_float(tf32(v.y));
            c4.z = __uint_as_float(tf32(v.z));
            c4.w = __uint_as_float(tf32(v.w));
            *(float4*)(W1sm + h*20 + kk) = c4;
        }
        __syncthreads();
        #pragma unroll
        for (int ks = 0; ks < 2; ks++) {
            int ka = kc*16 + ks*8 + tig;
            unsigned af[4][4];
            #pragma unroll
            for (int i = 0; i < 4; i++) {
                int r0 = i*16 + gid;
                af[i][0] = __float_as_uint(Ssm[r0*132 + ka]);
                af[i][1] = __float_as_uint(Ssm[(r0+8)*132 + ka]);
                af[i][2] = __float_as_uint(Ssm[r0*132 + ka + 4]);
                af[i][3] = __float_as_uint(Ssm[(r0+8)*132 + ka + 4]);
            }
            int kb = ks*8 + tig;
            #pragma unroll
            for (int jn = 0; jn < 4; jn++) {
                int n0 = n0w + jn*8;
                unsigned bf[2];
                bf[0] = __float_as_uint(W1sm[(n0+gid)*20 + kb]);
                bf[1] = __float_as_uint(W1sm[(n0+gid)*20 + kb + 4]);
                #pragma unroll
                for (int i = 0; i < 4; i++) mma8(acc1[i][jn], af[i], bf);
            }
        }
    }
    __syncthreads();   // done with W1sm region -> becomes Hsm
    // bias + GELU -> Hsm[g][h]
    #pragma unroll
    for (int jn = 0; jn < 4; jn++) {
        int n0 = n0w + jn*8;
        float bb0 = b1[n0 + 2*tig];
        float bb1 = b1[n0 + 2*tig + 1];
        #pragma unroll
        for (int i = 0; i < 4; i++) {
            int r0 = i*16 + gid;
            Hsm[r0*268     + n0 + 2*tig]     = gelu_exact(acc1[i][jn][0] + bb0);
            Hsm[r0*268     + n0 + 2*tig + 1] = gelu_exact(acc1[i][jn][1] + bb1);
            Hsm[(r0+8)*268 + n0 + 2*tig]     = gelu_exact(acc1[i][jn][2] + bb0);
            Hsm[(r0+8)*268 + n0 + 2*tig + 1] = gelu_exact(acc1[i][jn][3] + bb1);
        }
    }

    // ---- fc2: outT[64g][128d], warp w owns d in [w*16, w*16+16) ----
    float acc2[4][2][4];
    #pragma unroll
    for (int i = 0; i < 4; i++)
        #pragma unroll
        for (int jn = 0; jn < 2; jn++)
            #pragma unroll
            for (int c = 0; c < 4; c++) acc2[i][jn][c] = 0.f;
    int n0w2 = w * 16;
    for (int kc = 0; kc < 16; kc++) {      // K=256 in chunks of 16
        __syncthreads();
        #pragma unroll
        for (int r = 0; r < 2; r++) {      // stage W2[128][16] -> W2sm[128][20]
            int d  = r*64 + (t >> 2);
            int kk = (t & 3) * 4;
            float4 v = *(const float4*)(w2 + d*256 + kc*16 + kk);
            float4 c4;
            c4.x = __uint_as_float(tf32(v.x));
            c4.y = __uint_as_float(tf32(v.y));
            c4.z = __uint_as_float(tf32(v.z));
            c4.w = __uint_as_float(tf32(v.w));
            *(float4*)(W2sm + d*20 + kk) = c4;
        }
        __syncthreads();
        #pragma unroll
        for (int ks = 0; ks < 2; ks++) {
            int ka = kc*16 + ks*8 + tig;
            unsigned af[4][4];
            #pragma unroll
            for (int i = 0; i < 4; i++) {
                int r0 = i*16 + gid;
                af[i][0] = tf32(Hsm[r0*268 + ka]);
                af[i][1] = tf32(Hsm[(r0+8)*268 + ka]);
                af[i][2] = tf32(Hsm[r0*268 + ka + 4]);
                af[i][3] = tf32(Hsm[(r0+8)*268 + ka + 4]);
            }
            int kb = ks*8 + tig;
            #pragma unroll
            for (int jn = 0; jn < 2; jn++) {
                int n0 = n0w2 + jn*8;
                unsigned bf[2];
                bf[0] = __float_as_uint(W2sm[(n0+gid)*20 + kb]);
                bf[1] = __float_as_uint(W2sm[(n0+gid)*20 + kb + 4]);
                #pragma unroll
                for (int i = 0; i < 4; i++) mma8(acc2[i][jn], af[i], bf);
            }
        }
    }
    __syncthreads();   // done with W2sm region -> becomes Osm
    // transpose through Osm[d][g]  (stride 66)
    #pragma unroll
    for (int jn = 0; jn < 2; jn++) {
        int n0 = n0w2 + jn*8;
        #pragma unroll
        for (int i = 0; i < 4; i++) {
            int r0 = i*16 + gid;
            Osm[(n0+2*tig)*66   + r0]   = acc2[i][jn][0];
            Osm[(n0+2*tig+1)*66 + r0]   = acc2[i][jn][1];
            Osm[(n0+2*tig)*66   + r0+8] = acc2[i][jn][2];
            Osm[(n0+2*tig+1)*66 + r0+8] = acc2[i][jn][3];
        }
    }
    __syncthreads();
    // final: out = x + outT^T + b2 (coalesced float4 along g)
    {
        int d = t >> 1, gh = t & 1;
        float bias = b2[d];
        size_t obase = ((size_t)(b*ND + d))*NG + g0 + gh*32;
        const float* orow = Osm + d*66 + gh*32;
        #pragma unroll
        for (int j = 0; j < 8; j++) {
            float4 xv = *(const float4*)(x + obase + j*4);
            float4 res;
            res.x = xv.x + orow[j*4]     + bias;
            res.y = xv.y + orow[j*4 + 1] + bias;
            res.z = xv.z + orow[j*4 + 2] + bias;
            res.w = xv.w + orow[j*4 + 3] + bias;
            *(float4*)(out + obase + j*4) = res;
        }
    }
}

// ----------------------------------------------------------------
extern "C" void kernel_launch(void* const* d_in, const int* in_sizes, int n_in,
                              void* d_out, int out_size) {
    const float* x     = (const float*)d_in[0];
    const float* Phi   = (const float*)d_in[1];
    const float* Theta = (const float*)d_in[2];
    const float* gam   = (const float*)d_in[3];
    const float* bet   = (const float*)d_in[4];
    const float* w1    = (const float*)d_in[5];
    const float* b1    = (const float*)d_in[6];
    const float* w2    = (const float*)d_in[7];
    const float* b2    = (const float*)d_in[8];
    float* out = (float*)d_out;

    cudaFuncSetAttribute(k_mlp_tc, cudaFuncAttributeMaxDynamicSharedMemorySize, MLP_SMEM_BYTES);

    k_lnstats<<<dim3(16, 8), 512>>>(x);
    k_build_M<<<dim3(64, 33), 256>>>(Phi, Theta);
    k_fft_fwd<<<512, 512>>>(x, gam, bet);
    k_sf<<<NGF, 256>>>();
    k_ifft<<<512, 512>>>();
    k_mlp_tc<<<dim3(NG/64, NB), 256, MLP_SMEM_BYTES>>>(x, w1, b1, w2, b2, out);
}

// round 8
// speedup vs baseline: 4.0370x; 1.1545x over previous
#include <cuda_runtime.h>
#include <cuda_fp16.h>
#include <math.h>

#define NB 8
#define ND 128
#define NG 2048
#define NL 24
#define NGF 1025
#define NDD 16384   // D*D

// swizzled smem index for FFT: kills bit-reversal bank conflicts
#define IX(i) ((i) + ((i) >> 5))

// Scratch (device globals: allocation-free contract)
__device__ float  g_mean[NB*NG];
__device__ float  g_rstd[NB*NG];
__device__ float2 g_Xf[NGF*NB*ND];            // [f][b*128+d]
__device__ __half g_Mh[(size_t)NGF*NDD];      // [f][h][d]  33.6 MB (fp16)
__device__ float2 g_Sf[NB*ND*NGF];            // [b*128+h][f]
__device__ float  g_S [NB*ND*NG];             // [b*128+h][g]

// ---------------------------------------------------------------- mma helpers
__device__ __forceinline__ unsigned tf32(float v) {
    unsigned u; asm("cvt.rna.tf32.f32 %0, %1;" : "=r"(u) : "f"(v)); return u;
}
__device__ __forceinline__ void mma8(float* c, const unsigned* a, const unsigned* b) {
    asm volatile("mma.sync.aligned.m16n8k8.row.col.f32.tf32.tf32.f32 "
        "{%0,%1,%2,%3},{%4,%5,%6,%7},{%8,%9},{%0,%1,%2,%3};"
        : "+f"(c[0]), "+f"(c[1]), "+f"(c[2]), "+f"(c[3])
        : "r"(a[0]), "r"(a[1]), "r"(a[2]), "r"(a[3]), "r"(b[0]), "r"(b[1]));
}
__device__ __forceinline__ void mma16h(float* c, const unsigned* a, unsigned b0, unsigned b1) {
    asm volatile("mma.sync.aligned.m16n8k16.row.col.f32.f16.f16.f32 "
        "{%0,%1,%2,%3},{%4,%5,%6,%7},{%8,%9},{%0,%1,%2,%3};"
        : "+f"(c[0]), "+f"(c[1]), "+f"(c[2]), "+f"(c[3])
        : "r"(a[0]), "r"(a[1]), "r"(a[2]), "r"(a[3]), "r"(b0), "r"(b1));
}
__device__ __forceinline__ float gelu_exact(float v) {
    return 0.5f*v*(1.f + erff(v*0.70710678118654752f));
}

// ---------------------------------------------------------------- LN stats (4-way d split)
__global__ void k_lnstats(const float* __restrict__ x) {
    __shared__ float ps[4*128], pss[4*128];
    int t = threadIdx.x;               // 512
    int g = t & 127, dq = t >> 7;      // dq 0..3
    int b = blockIdx.y;
    int g0 = blockIdx.x * 128;
    const float* p = x + (size_t)b*ND*NG + (size_t)(dq*32)*NG + g0 + g;
    float s = 0.f, ss = 0.f;
    #pragma unroll 8
    for (int d = 0; d < 32; d++) { float v = p[(size_t)d*NG]; s += v; ss += v*v; }
    ps[dq*128+g] = s; pss[dq*128+g] = ss;
    __syncthreads();
    if (dq == 0) {
        float S  = ps[g]  + ps[128+g]  + ps[256+g]  + ps[384+g];
        float SS = pss[g] + pss[128+g] + pss[256+g] + pss[384+g];
        float mean = S * (1.f/ND);
        float var  = SS * (1.f/ND) - mean*mean;
        g_mean[b*NG + g0 + g] = mean;
        g_rstd[b*NG + g0 + g] = rsqrtf(var + 1e-5f);
    }
}

// ---------------------------------------------------------------- radix-4 fused FFT 2048 (512 threads)
__device__ __forceinline__ void fft2048_r4(float* re, float* im, const float2* tw, int inv) {
    int t = threadIdx.x;   // 512
    __syncthreads();
    #pragma unroll
    for (int j = 0; j < 2; j++) {
        int k = t + j*512;
        int i0 = IX(2*k), i1 = IX(2*k+1);
        float ar = re[i0], ai = im[i0], br = re[i1], bi = im[i1];
        re[i0] = ar+br; im[i0] = ai+bi;
        re[i1] = ar-br; im[i1] = ai-bi;
    }
    #pragma unroll
    for (int s = 0; s < 5; s++) {
        int lq = 2*s + 1;
        int q  = 1 << lq;
        __syncthreads();
        int pos = t & (q-1);
        int i0l = ((t >> lq) << (lq+2)) + pos;
        int i0 = IX(i0l), i1 = IX(i0l+q), i2 = IX(i0l+2*q), i3 = IX(i0l+3*q);
        float2 w1 = tw[pos << (10-lq)];
        float2 w2 = tw[pos << (9-lq)];
        if (inv) { w1.y = -w1.y; w2.y = -w2.y; }
        float w3x = inv ? -w2.y : w2.y;
        float w3y = inv ?  w2.x : -w2.x;
        float x0r=re[i0], x0i=im[i0];
        float x1r=re[i1], x1i=im[i1];
        float x2r=re[i2], x2i=im[i2];
        float x3r=re[i3], x3i=im[i3];
        float a1r = w1.x*x1r - w1.y*x1i, a1i = w1.x*x1i + w1.y*x1r;
        float a3r = w1.x*x3r - w1.y*x3i, a3i = w1.x*x3i + w1.y*x3r;
        float u0r = x0r+a1r, u0i = x0i+a1i;
        float u1r = x0r-a1r, u1i = x0i-a1i;
        float u2r = x2r+a3r, u2i = x2i+a3i;
        float u3r = x2r-a3r, u3i = x2i-a3i;
        float b2r = w2.x*u2r - w2.y*u2i, b2i = w2.x*u2i + w2.y*u2r;
        float b3r = w3x*u3r - w3y*u3i,  b3i = w3x*u3i + w3y*u3r;
        re[i0]=u0r+b2r; im[i0]=u0i+b2i;
        re[i2]=u0r-b2r; im[i2]=u0i-b2i;
        re[i1]=u1r+b3r; im[i1]=u1i+b3i;
        re[i3]=u1r-b3r; im[i3]=u1i-b3i;
    }
    __syncthreads();
}

// ---------------------------------------------------------------- LN-apply + packed real FFT
__global__ void k_fft_fwd(const float* __restrict__ x,
                          const float* __restrict__ gamma,
                          const float* __restrict__ beta) {
    __shared__ float re[2112], im[2112];
    __shared__ float2 tw[1024];
    int t = threadIdx.x;   // 512
    int row0 = blockIdx.x*2, row1 = row0 + 1;
    int b = row0 >> 7;
    int d0 = row0 & 127, d1 = d0 + 1;
    for (int j = t; j < 1024; j += 512) {
        float sv, cv;
        __sincosf(-6.2831853071795864769f * (float)j * (1.f/2048.f), &sv, &cv);
        tw[j] = make_float2(cv, sv);
    }
    const float* xp0 = x + (size_t)row0*NG;
    const float* xp1 = x + (size_t)row1*NG;
    const float* mp  = g_mean + b*NG;
    const float* rp  = g_rstd + b*NG;
    float ga0 = gamma[d0], be0 = beta[d0], ga1 = gamma[d1], be1 = beta[d1];
    #pragma unroll
    for (int j = 0; j < 4; j++) {
        int i = t + j*512;
        float m = mp[i], r = rp[i];
        float z0 = (xp0[i]-m)*r*ga0 + be0;
        float z1 = (xp1[i]-m)*r*ga1 + be1;
        int rv = __brev(i) >> 21;
        re[IX(rv)] = z0; im[IX(rv)] = z1;
    }
    fft2048_r4(re, im, tw, 0);
    for (int k = t; k <= 1024; k += 512) {
        int km = (2048 - k) & 2047;
        float zr = re[IX(k)],  zi = im[IX(k)];
        float mr = re[IX(km)], mi = im[IX(km)];
        float2 A  = make_float2(0.5f*(zr+mr), 0.5f*(zi-mi));
        float2 Bv = make_float2(0.5f*(zi+mi), 0.5f*(mr-zr));
        g_Xf[k*(NB*ND) + row0] = A;
        g_Xf[k*(NB*ND) + row1] = Bv;
    }
}

// ---------------------------------------------------------------- M[f,h,d] = sum_l Phi[l,f]*Theta[l,h,d]  (fp16 out)
__global__ void k_build_M(const float* __restrict__ Phi, const float* __restrict__ Theta) {
    __shared__ float sphi[NL*32];
    int t  = threadIdx.x;
    int i  = blockIdx.x*256 + t;      // h*128+d
    int f0 = blockIdx.y*32;
    for (int idx = t; idx < NL*32; idx += 256) {
        int l = idx >> 5, ff = idx & 31;
        sphi[idx] = (f0+ff < NGF) ? Phi[l*NGF + f0 + ff] : 0.f;
    }
    __syncthreads();
    float th[NL];
    #pragma unroll
    for (int l = 0; l < NL; l++) th[l] = Theta[l*NDD + i];
    float4 acc[8];
    #pragma unroll
    for (int j = 0; j < 8; j++) acc[j] = make_float4(0.f,0.f,0.f,0.f);
    #pragma unroll
    for (int l = 0; l < NL; l++) {
        const float4* sp = (const float4*)(sphi + l*32);
        float tl = th[l];
        #pragma unroll
        for (int j = 0; j < 8; j++) {
            float4 p = sp[j];
            acc[j].x += p.x*tl; acc[j].y += p.y*tl;
            acc[j].z += p.z*tl; acc[j].w += p.w*tl;
        }
    }
    #pragma unroll
    for (int j = 0; j < 8; j++) {
        float v[4] = {acc[j].x, acc[j].y, acc[j].z, acc[j].w};
        #pragma unroll
        for (int c = 0; c < 4; c++) {
            int ff = f0 + j*4 + c;
            if (ff < NGF) g_Mh[(size_t)ff*NDD + i] = __float2half_rn(v[c]);
        }
    }
}

// ---------------------------------------------------------------- S_f: tensor-core version
// Per block: one f. C[128h x 16n] = M[f](128h x 128d, fp16) * X(128d x 16n, fp16)
// n = 2*b + (0:re, 1:im). fp32 accumulate. 8 warps, warp w owns h in [16w, 16w+16).
#define MPAD 136   // halves per smem row (272B: conflict-free frag loads)
__global__ void __launch_bounds__(256) k_sf_mma() {
    __shared__ __half Msm[128*MPAD];   // 34816 B
    __shared__ __half Xsm[16*MPAD];    // 4352 B
    int t = threadIdx.x;       // 256
    int f = blockIdx.x;

    // stage M via cp.async: 128 rows x 16 chunks of 16B
    {
        const char* src = (const char*)(g_Mh + (size_t)f*NDD);
        unsigned sbase = (unsigned)__cvta_generic_to_shared(Msm);
        #pragma unroll
        for (int j = 0; j < 8; j++) {
            int idx = t + j*256;        // 0..2047
            int row = idx >> 4, c = idx & 15;
            unsigned dst = sbase + row*(MPAD*2) + c*16;
            asm volatile("cp.async.cg.shared.global [%0], [%1], 16;"
                         :: "r"(dst), "l"(src + row*256 + c*16));
        }
        asm volatile("cp.async.commit_group;");
    }
    // stage X transposed (fp32 -> fp16): Xsm[n = 2b+reim][d]
    #pragma unroll
    for (int j = 0; j < 4; j++) {
        int idx = t + j*256;            // b*128 + d
        float2 v = g_Xf[f*1024 + idx];
        int b = idx >> 7, d = idx & 127;
        Xsm[(2*b)*MPAD + d]   = __float2half_rn(v.x);
        Xsm[(2*b+1)*MPAD + d] = __float2half_rn(v.y);
    }
    asm volatile("cp.async.wait_group 0;");
    __syncthreads();

    int lane = t & 31, w = t >> 5;
    int gid = lane >> 2, tig = lane & 3;
    int h0 = w * 16;
    float c[2][4];
    #pragma unroll
    for (int j = 0; j < 2; j++)
        #pragma unroll
        for (int q = 0; q < 4; q++) c[j][q] = 0.f;

    const __half* Arow0 = Msm + (h0 + gid)*MPAD;
    const __half* Arow1 = Msm + (h0 + gid + 8)*MPAD;
    #pragma unroll
    for (int kc = 0; kc < 8; kc++) {
        int k0 = kc*16 + 2*tig;
        unsigned a[4];
        a[0] = *(const unsigned*)(Arow0 + k0);
        a[1] = *(const unsigned*)(Arow1 + k0);
        a[2] = *(const unsigned*)(Arow0 + k0 + 8);
        a[3] = *(const unsigned*)(Arow1 + k0 + 8);
        #pragma unroll
        for (int j = 0; j < 2; j++) {
            int n = j*8 + gid;
            unsigned b0 = *(const unsigned*)(Xsm + n*MPAD + k0);
            unsigned b1 = *(const unsigned*)(Xsm + n*MPAD + k0 + 8);
            mma16h(c[j], a, b0, b1);
        }
    }
    // store: C cols n0+2tig (re), n0+2tig+1 (im) -> b = 4j + tig
    #pragma unroll
    for (int j = 0; j < 2; j++) {
        int b = 4*j + tig;
        int h_lo = h0 + gid, h_hi = h_lo + 8;
        g_Sf[(size_t)(b*ND + h_lo)*NGF + f] = make_float2(c[j][0], c[j][1]);
        g_Sf[(size_t)(b*ND + h_hi)*NGF + f] = make_float2(c[j][2], c[j][3]);
    }
}

// ---------------------------------------------------------------- packed irfft
__global__ void k_ifft() {
    __shared__ float re[2112], im[2112];
    __shared__ float2 tw[1024];
    int t = threadIdx.x;   // 512
    int row0 = blockIdx.x*2, row1 = row0 + 1;
    for (int j = t; j < 1024; j += 512) {
        float sv, cv;
        __sincosf(-6.2831853071795864769f * (float)j * (1.f/2048.f), &sv, &cv);
        tw[j] = make_float2(cv, sv);
    }
    const float2* p0 = g_Sf + (size_t)row0*NGF;
    const float2* p1 = g_Sf + (size_t)row1*NGF;
    #pragma unroll
    for (int j = 0; j < 4; j++) {
        int i = t + j*512;
        int src = (i <= 1024) ? i : 2048 - i;
        float2 v0 = p0[src], v1 = p1[src];
        if (i > 1024) { v0.y = -v0.y; v1.y = -v1.y; }
        int rv = __brev(i) >> 21;
        re[IX(rv)] = v0.x - v1.y;
        im[IX(rv)] = v0.y + v1.x;
    }
    fft2048_r4(re, im, tw, 1);
    const float sc = 1.0f/2048.0f;
    #pragma unroll
    for (int j = 0; j < 4; j++) {
        int i = t + j*512;
        g_S[(size_t)row0*NG + i] = re[IX(i)]*sc;
        g_S[(size_t)row1*NG + i] = im[IX(i)]*sc;
    }
}

// ---------------------------------------------------------------- tensor-core MLP (tf32 mma), g-tile 64
#define MLP_SMEM_BYTES ((8448 + 17152)*4)
__global__ void __launch_bounds__(256) k_mlp_tc(
        const float* __restrict__ x,
        const float* __restrict__ w1, const float* __restrict__ b1,
        const float* __restrict__ w2, const float* __restrict__ b2,
        float* __restrict__ out) {
    extern __shared__ float buf[];
    float* Ssm = buf;          // [64][132]
    float* Hsm = buf + 8448;   // [64][268]
    float* W1sm = Hsm;         // alias during fc1 k-loop: [256][20]
    float* W2sm = Ssm;         // alias during fc2 k-loop: [128][20]
    float* Osm  = Ssm;         // alias at epilogue: [128][66]

    int t = threadIdx.x;           // 256
    int lane = t & 31, w = t >> 5; // 8 warps
    int gid = lane >> 2, tig = lane & 3;
    int b = blockIdx.y, g0 = blockIdx.x * 64;

    // ---- load S tile transposed into Ssm[g][d] as tf32 ----
    {
        int d = t & 127, gq = t >> 7;
        const float* src = g_S + ((size_t)(b*ND + d))*NG + g0 + gq*32;
        #pragma unroll
        for (int j = 0; j < 8; j++) {
            float4 v = *(const float4*)(src + j*4);
            int gg = gq*32 + j*4;
            Ssm[(gg+0)*132 + d] = __uint_as_float(tf32(v.x));
            Ssm[(gg+1)*132 + d] = __uint_as_float(tf32(v.y));
            Ssm[(gg+2)*132 + d] = __uint_as_float(tf32(v.z));
            Ssm[(gg+3)*132 + d] = __uint_as_float(tf32(v.w));
        }
    }

    // ---- fc1: Ht[64g][256h], warp w owns h in [w*32, w*32+32) ----
    float acc1[4][4][4];
    #pragma unroll
    for (int i = 0; i < 4; i++)
        #pragma unroll
        for (int jn = 0; jn < 4; jn++)
            #pragma unroll
            for (int c = 0; c < 4; c++) acc1[i][jn][c] = 0.f;
    int n0w = w * 32;
    for (int kc = 0; kc < 8; kc++) {
        __syncthreads();
        #pragma unroll
        for (int r = 0; r < 4; r++) {
            int h  = r*64 + (t >> 2);
            int kk = (t & 3) * 4;
            float4 v = *(const float4*)(w1 + h*128 + kc*16 + kk);
            float4 c4;
            c4.x = __uint_as_float(tf32(v.x));
            c4.y = __uint_as_float(tf32(v.y));
            c4.z = __uint_as_float(tf32(v.z));
            c4.w = __uint_as_float(tf32(v.w));
            *(float4*)(W1sm + h*20 + kk) = c4;
        }
        __syncthreads();
        #pragma unroll
        for (int ks = 0; ks < 2; ks++) {
            int ka = kc*16 + ks*8 + tig;
            unsigned af[4][4];
            #pragma unroll
            for (int i = 0; i < 4; i++) {
                int r0 = i*16 + gid;
                af[i][0] = __float_as_uint(Ssm[r0*132 + ka]);
                af[i][1] = __float_as_uint(Ssm[(r0+8)*132 + ka]);
                af[i][2] = __float_as_uint(Ssm[r0*132 + ka + 4]);
                af[i][3] = __float_as_uint(Ssm[(r0+8)*132 + ka + 4]);
            }
            int kb = ks*8 + tig;
            #pragma unroll
            for (int jn = 0; jn < 4; jn++) {
                int n0 = n0w + jn*8;
                unsigned bf[2];
                bf[0] = __float_as_uint(W1sm[(n0+gid)*20 + kb]);
                bf[1] = __float_as_uint(W1sm[(n0+gid)*20 + kb + 4]);
                #pragma unroll
                for (int i = 0; i < 4; i++) mma8(acc1[i][jn], af[i], bf);
            }
        }
    }
    __syncthreads();
    // bias + GELU -> Hsm[g][h]
    #pragma unroll
    for (int jn = 0; jn < 4; jn++) {
        int n0 = n0w + jn*8;
        float bb0 = b1[n0 + 2*tig];
        float bb1 = b1[n0 + 2*tig + 1];
        #pragma unroll
        for (int i = 0; i < 4; i++) {
            int r0 = i*16 + gid;
            Hsm[r0*268     + n0 + 2*tig]     = gelu_exact(acc1[i][jn][0] + bb0);
            Hsm[r0*268     + n0 + 2*tig + 1] = gelu_exact(acc1[i][jn][1] + bb1);
            Hsm[(r0+8)*268 + n0 + 2*tig]     = gelu_exact(acc1[i][jn][2] + bb0);
            Hsm[(r0+8)*268 + n0 + 2*tig + 1] = gelu_exact(acc1[i][jn][3] + bb1);
        }
    }

    // ---- fc2: outT[64g][128d], warp w owns d in [w*16, w*16+16) ----
    float acc2[4][2][4];
    #pragma unroll
    for (int i = 0; i < 4; i++)
        #pragma unroll
        for (int jn = 0; jn < 2; jn++)
            #pragma unroll
            for (int c = 0; c < 4; c++) acc2[i][jn][c] = 0.f;
    int n0w2 = w * 16;
    for (int kc = 0; kc < 16; kc++) {
        __syncthreads();
        #pragma unroll
        for (int r = 0; r < 2; r++) {
            int d  = r*64 + (t >> 2);
            int kk = (t & 3) * 4;
            float4 v = *(const float4*)(w2 + d*256 + kc*16 + kk);
            float4 c4;
            c4.x = __uint_as_float(tf32(v.x));
            c4.y = __uint_as_float(tf32(v.y));
            c4.z = __uint_as_float(tf32(v.z));
            c4.w = __uint_as_float(tf32(v.w));
            *(float4*)(W2sm + d*20 + kk) = c4;
        }
        __syncthreads();
        #pragma unroll
        for (int ks = 0; ks < 2; ks++) {
            int ka = kc*16 + ks*8 + tig;
            unsigned af[4][4];
            #pragma unroll
            for (int i = 0; i < 4; i++) {
                int r0 = i*16 + gid;
                af[i][0] = tf32(Hsm[r0*268 + ka]);
                af[i][1] = tf32(Hsm[(r0+8)*268 + ka]);
                af[i][2] = tf32(Hsm[r0*268 + ka + 4]);
                af[i][3] = tf32(Hsm[(r0+8)*268 + ka + 4]);
            }
            int kb = ks*8 + tig;
            #pragma unroll
            for (int jn = 0; jn < 2; jn++) {
                int n0 = n0w2 + jn*8;
                unsigned bf[2];
                bf[0] = __float_as_uint(W2sm[(n0+gid)*20 + kb]);
                bf[1] = __float_as_uint(W2sm[(n0+gid)*20 + kb + 4]);
                #pragma unroll
                for (int i = 0; i < 4; i++) mma8(acc2[i][jn], af[i], bf);
            }
        }
    }
    __syncthreads();
    // transpose through Osm[d][g]  (stride 66)
    #pragma unroll
    for (int jn = 0; jn < 2; jn++) {
        int n0 = n0w2 + jn*8;
        #pragma unroll
        for (int i = 0; i < 4; i++) {
            int r0 = i*16 + gid;
            Osm[(n0+2*tig)*66   + r0]   = acc2[i][jn][0];
            Osm[(n0+2*tig+1)*66 + r0]   = acc2[i][jn][1];
            Osm[(n0+2*tig)*66   + r0+8] = acc2[i][jn][2];
            Osm[(n0+2*tig+1)*66 + r0+8] = acc2[i][jn][3];
        }
    }
    __syncthreads();
    // final: out = x + outT^T + b2 (coalesced float4 along g)
    {
        int d = t >> 1, gh = t & 1;
        float bias = b2[d];
        size_t obase = ((size_t)(b*ND + d))*NG + g0 + gh*32;
        const float* orow = Osm + d*66 + gh*32;
        #pragma unroll
        for (int j = 0; j < 8; j++) {
            float4 xv = *(const float4*)(x + obase + j*4);
            float4 res;
            res.x = xv.x + orow[j*4]     + bias;
            res.y = xv.y + orow[j*4 + 1] + bias;
            res.z = xv.z + orow[j*4 + 2] + bias;
            res.w = xv.w + orow[j*4 + 3] + bias;
            *(float4*)(out + obase + j*4) = res;
        }
    }
}

// ----------------------------------------------------------------
extern "C" void kernel_launch(void* const* d_in, const int* in_sizes, int n_in,
                              void* d_out, int out_size) {
    const float* x     = (const float*)d_in[0];
    const float* Phi   = (const float*)d_in[1];
    const float* Theta = (const float*)d_in[2];
    const float* gam   = (const float*)d_in[3];
    const float* bet   = (const float*)d_in[4];
    const float* w1    = (const float*)d_in[5];
    const float* b1    = (const float*)d_in[6];
    const float* w2    = (const float*)d_in[7];
    const float* b2    = (const float*)d_in[8];
    float* out = (float*)d_out;

    cudaFuncSetAttribute(k_mlp_tc, cudaFuncAttributeMaxDynamicSharedMemorySize, MLP_SMEM_BYTES);

    k_lnstats<<<dim3(16, 8), 512>>>(x);
    k_build_M<<<dim3(64, 33), 256>>>(Phi, Theta);
    k_fft_fwd<<<512, 512>>>(x, gam, bet);
    k_sf_mma<<<NGF, 256>>>();
    k_ifft<<<512, 512>>>();
    k_mlp_tc<<<dim3(NG/64, NB), 256, MLP_SMEM_BYTES>>>(x, w1, b1, w2, b2, out);
}

// round 12
// speedup vs baseline: 4.5608x; 1.1297x over previous
#include <cuda_runtime.h>
#include <cuda_fp16.h>
#include <math.h>

#define NB 8
#define ND 128
#define NG 2048
#define NL 24
#define NGF 1025
#define NDD 16384   // D*D

// swizzled smem index for FFT: kills bit-reversal bank conflicts
#define IX(i) ((i) + ((i) >> 5))

// Scratch (device globals: allocation-free contract)
__device__ float  g_mean[NB*NG];
__device__ float  g_rstd[NB*NG];
__device__ float2 g_Xf[NGF*NB*ND];            // [f][b*128+d]
__device__ __half g_Mh[(size_t)NGF*NDD];      // [f][h][d]  33.6 MB (fp16)
__device__ float2 g_Sf[NB*ND*NGF];            // [b*128+h][f]
__device__ float  g_S [NB*ND*NG];             // [b*128+h][g]

// ---------------------------------------------------------------- mma helpers
__device__ __forceinline__ void mma16h(float* c, const unsigned* a, unsigned b0, unsigned b1) {
    asm volatile("mma.sync.aligned.m16n8k16.row.col.f32.f16.f16.f32 "
        "{%0,%1,%2,%3},{%4,%5,%6,%7},{%8,%9},{%0,%1,%2,%3};"
        : "+f"(c[0]), "+f"(c[1]), "+f"(c[2]), "+f"(c[3])
        : "r"(a[0]), "r"(a[1]), "r"(a[2]), "r"(a[3]), "r"(b0), "r"(b1));
}
__device__ __forceinline__ float gelu_exact(float v) {
    return 0.5f*v*(1.f + erff(v*0.70710678118654752f));
}
__device__ __forceinline__ unsigned h2u(__half2 h) { return *(unsigned*)&h; }

// ---------------------------------------------------------------- LN stats (4-way d split)
__global__ void k_lnstats(const float* __restrict__ x) {
    __shared__ float ps[4*128], pss[4*128];
    int t = threadIdx.x;               // 512
    int g = t & 127, dq = t >> 7;      // dq 0..3
    int b = blockIdx.y;
    int g0 = blockIdx.x * 128;
    const float* p = x + (size_t)b*ND*NG + (size_t)(dq*32)*NG + g0 + g;
    float s = 0.f, ss = 0.f;
    #pragma unroll 8
    for (int d = 0; d < 32; d++) { float v = p[(size_t)d*NG]; s += v; ss += v*v; }
    ps[dq*128+g] = s; pss[dq*128+g] = ss;
    __syncthreads();
    if (dq == 0) {
        float S  = ps[g]  + ps[128+g]  + ps[256+g]  + ps[384+g];
        float SS = pss[g] + pss[128+g] + pss[256+g] + pss[384+g];
        float mean = S * (1.f/ND);
        float var  = SS * (1.f/ND) - mean*mean;
        g_mean[b*NG + g0 + g] = mean;
        g_rstd[b*NG + g0 + g] = rsqrtf(var + 1e-5f);
    }
}

// ---------------------------------------------------------------- radix-4 fused FFT 2048 (512 threads)
__device__ __forceinline__ void fft2048_r4(float* re, float* im, const float2* tw, int inv) {
    int t = threadIdx.x;   // 512
    __syncthreads();
    #pragma unroll
    for (int j = 0; j < 2; j++) {
        int k = t + j*512;
        int i0 = IX(2*k), i1 = IX(2*k+1);
        float ar = re[i0], ai = im[i0], br = re[i1], bi = im[i1];
        re[i0] = ar+br; im[i0] = ai+bi;
        re[i1] = ar-br; im[i1] = ai-bi;
    }
    #pragma unroll
    for (int s = 0; s < 5; s++) {
        int lq = 2*s + 1;
        int q  = 1 << lq;
        __syncthreads();
        int pos = t & (q-1);
        int i0l = ((t >> lq) << (lq+2)) + pos;
        int i0 = IX(i0l), i1 = IX(i0l+q), i2 = IX(i0l+2*q), i3 = IX(i0l+3*q);
        float2 w1 = tw[pos << (10-lq)];
        float2 w2 = tw[pos << (9-lq)];
        if (inv) { w1.y = -w1.y; w2.y = -w2.y; }
        float w3x = inv ? -w2.y : w2.y;
        float w3y = inv ?  w2.x : -w2.x;
        float x0r=re[i0], x0i=im[i0];
        float x1r=re[i1], x1i=im[i1];
        float x2r=re[i2], x2i=im[i2];
        float x3r=re[i3], x3i=im[i3];
        float a1r = w1.x*x1r - w1.y*x1i, a1i = w1.x*x1i + w1.y*x1r;
        float a3r = w1.x*x3r - w1.y*x3i, a3i = w1.x*x3i + w1.y*x3r;
        float u0r = x0r+a1r, u0i = x0i+a1i;
        float u1r = x0r-a1r, u1i = x0i-a1i;
        float u2r = x2r+a3r, u2i = x2i+a3i;
        float u3r = x2r-a3r, u3i = x2i-a3i;
        float b2r = w2.x*u2r - w2.y*u2i, b2i = w2.x*u2i + w2.y*u2r;
        float b3r = w3x*u3r - w3y*u3i,  b3i = w3x*u3i + w3y*u3r;
        re[i0]=u0r+b2r; im[i0]=u0i+b2i;
        re[i2]=u0r-b2r; im[i2]=u0i-b2i;
        re[i1]=u1r+b3r; im[i1]=u1i+b3i;
        re[i3]=u1r-b3r; im[i3]=u1i-b3i;
    }
    __syncthreads();
}

// ---------------------------------------------------------------- LN-apply + packed real FFT
__global__ void k_fft_fwd(const float* __restrict__ x,
                          const float* __restrict__ gamma,
                          const float* __restrict__ beta) {
    __shared__ float re[2112], im[2112];
    __shared__ float2 tw[1024];
    int t = threadIdx.x;   // 512
    int row0 = blockIdx.x*2, row1 = row0 + 1;
    int b = row0 >> 7;
    int d0 = row0 & 127, d1 = d0 + 1;
    for (int j = t; j < 1024; j += 512) {
        float sv, cv;
        __sincosf(-6.2831853071795864769f * (float)j * (1.f/2048.f), &sv, &cv);
        tw[j] = make_float2(cv, sv);
    }
    const float* xp0 = x + (size_t)row0*NG;
    const float* xp1 = x + (size_t)row1*NG;
    const float* mp  = g_mean + b*NG;
    const float* rp  = g_rstd + b*NG;
    float ga0 = gamma[d0], be0 = beta[d0], ga1 = gamma[d1], be1 = beta[d1];
    #pragma unroll
    for (int j = 0; j < 4; j++) {
        int i = t + j*512;
        float m = mp[i], r = rp[i];
        float z0 = (xp0[i]-m)*r*ga0 + be0;
        float z1 = (xp1[i]-m)*r*ga1 + be1;
        int rv = __brev(i) >> 21;
        re[IX(rv)] = z0; im[IX(rv)] = z1;
    }
    fft2048_r4(re, im, tw, 0);
    for (int k = t; k <= 1024; k += 512) {
        int km = (2048 - k) & 2047;
        float zr = re[IX(k)],  zi = im[IX(k)];
        float mr = re[IX(km)], mi = im[IX(km)];
        float2 A  = make_float2(0.5f*(zr+mr), 0.5f*(zi-mi));
        float2 Bv = make_float2(0.5f*(zi+mi), 0.5f*(mr-zr));
        g_Xf[k*(NB*ND) + row0] = A;
        g_Xf[k*(NB*ND) + row1] = Bv;
    }
}

// ---------------------------------------------------------------- M[f,h,d] = sum_l Phi[l,f]*Theta[l,h,d]  (fp16 out)
__global__ void k_build_M(const float* __restrict__ Phi, const float* __restrict__ Theta) {
    __shared__ float sphi[NL*32];
    int t  = threadIdx.x;
    int i  = blockIdx.x*256 + t;      // h*128+d
    int f0 = blockIdx.y*32;
    for (int idx = t; idx < NL*32; idx += 256) {
        int l = idx >> 5, ff = idx & 31;
        sphi[idx] = (f0+ff < NGF) ? Phi[l*NGF + f0 + ff] : 0.f;
    }
    __syncthreads();
    float th[NL];
    #pragma unroll
    for (int l = 0; l < NL; l++) th[l] = Theta[l*NDD + i];
    float4 acc[8];
    #pragma unroll
    for (int j = 0; j < 8; j++) acc[j] = make_float4(0.f,0.f,0.f,0.f);
    #pragma unroll
    for (int l = 0; l < NL; l++) {
        const float4* sp = (const float4*)(sphi + l*32);
        float tl = th[l];
        #pragma unroll
        for (int j = 0; j < 8; j++) {
            float4 p = sp[j];
            acc[j].x += p.x*tl; acc[j].y += p.y*tl;
            acc[j].z += p.z*tl; acc[j].w += p.w*tl;
        }
    }
    #pragma unroll
    for (int j = 0; j < 8; j++) {
        float v[4] = {acc[j].x, acc[j].y, acc[j].z, acc[j].w};
        #pragma unroll
        for (int c = 0; c < 4; c++) {
            int ff = f0 + j*4 + c;
            if (ff < NGF) g_Mh[(size_t)ff*NDD + i] = __float2half_rn(v[c]);
        }
    }
}

// ---------------------------------------------------------------- S_f: tensor-core version (round-8 proven)
// Per block: one f. C[128h x 16n] = M[f](128h x 128d, fp16) * X(128d x 16n, fp16)
// n = 2*b + (0:re, 1:im). fp32 accumulate. 8 warps, warp w owns h in [16w, 16w+16).
#define MPAD 136   // halves per smem row (272B: conflict-free frag loads)
__global__ void __launch_bounds__(256) k_sf_mma() {
    __shared__ __half Msm[128*MPAD];   // 34816 B
    __shared__ __half Xsm[16*MPAD];    // 4352 B
    int t = threadIdx.x;       // 256
    int f = blockIdx.x;

    // stage M via cp.async: 128 rows x 16 chunks of 16B
    {
        const char* src = (const char*)(g_Mh + (size_t)f*NDD);
        unsigned sbase = (unsigned)__cvta_generic_to_shared(Msm);
        #pragma unroll
        for (int j = 0; j < 8; j++) {
            int idx = t + j*256;        // 0..2047
            int row = idx >> 4, c = idx & 15;
            unsigned dst = sbase + row*(MPAD*2) + c*16;
            asm volatile("cp.async.cg.shared.global [%0], [%1], 16;"
                         :: "r"(dst), "l"(src + row*256 + c*16));
        }
        asm volatile("cp.async.commit_group;");
    }
    // stage X transposed (fp32 -> fp16): Xsm[n = 2b+reim][d]
    #pragma unroll
    for (int j = 0; j < 4; j++) {
        int idx = t + j*256;            // b*128 + d
        float2 v = g_Xf[f*1024 + idx];
        int b = idx >> 7, d = idx & 127;
        Xsm[(2*b)*MPAD + d]   = __float2half_rn(v.x);
        Xsm[(2*b+1)*MPAD + d] = __float2half_rn(v.y);
    }
    asm volatile("cp.async.wait_group 0;");
    __syncthreads();

    int lane = t & 31, w = t >> 5;
    int gid = lane >> 2, tig = lane & 3;
    int h0 = w * 16;
    float c[2][4];
    #pragma unroll
    for (int j = 0; j < 2; j++)
        #pragma unroll
        for (int q = 0; q < 4; q++) c[j][q] = 0.f;

    const __half* Arow0 = Msm + (h0 + gid)*MPAD;
    const __half* Arow1 = Msm + (h0 + gid + 8)*MPAD;
    #pragma unroll
    for (int kc = 0; kc < 8; kc++) {
        int k0 = kc*16 + 2*tig;
        unsigned a[4];
        a[0] = *(const unsigned*)(Arow0 + k0);
        a[1] = *(const unsigned*)(Arow1 + k0);
        a[2] = *(const unsigned*)(Arow0 + k0 + 8);
        a[3] = *(const unsigned*)(Arow1 + k0 + 8);
        #pragma unroll
        for (int j = 0; j < 2; j++) {
            int n = j*8 + gid;
            unsigned b0 = *(const unsigned*)(Xsm + n*MPAD + k0);
            unsigned b1 = *(const unsigned*)(Xsm + n*MPAD + k0 + 8);
            mma16h(c[j], a, b0, b1);
        }
    }
    // store: C cols n0+2tig (re), n0+2tig+1 (im) -> b = 4j + tig
    #pragma unroll
    for (int j = 0; j < 2; j++) {
        int b = 4*j + tig;
        int h_lo = h0 + gid, h_hi = h_lo + 8;
        g_Sf[(size_t)(b*ND + h_lo)*NGF + f] = make_float2(c[j][0], c[j][1]);
        g_Sf[(size_t)(b*ND + h_hi)*NGF + f] = make_float2(c[j][2], c[j][3]);
    }
}

// ---------------------------------------------------------------- packed irfft
__global__ void k_ifft() {
    __shared__ float re[2112], im[2112];
    __shared__ float2 tw[1024];
    int t = threadIdx.x;   // 512
    int row0 = blockIdx.x*2, row1 = row0 + 1;
    for (int j = t; j < 1024; j += 512) {
        float sv, cv;
        __sincosf(-6.2831853071795864769f * (float)j * (1.f/2048.f), &sv, &cv);
        tw[j] = make_float2(cv, sv);
    }
    const float2* p0 = g_Sf + (size_t)row0*NGF;
    const float2* p1 = g_Sf + (size_t)row1*NGF;
    #pragma unroll
    for (int j = 0; j < 4; j++) {
        int i = t + j*512;
        int src = (i <= 1024) ? i : 2048 - i;
        float2 v0 = p0[src], v1 = p1[src];
        if (i > 1024) { v0.y = -v0.y; v1.y = -v1.y; }
        int rv = __brev(i) >> 21;
        re[IX(rv)] = v0.x - v1.y;
        im[IX(rv)] = v0.y + v1.x;
    }
    fft2048_r4(re, im, tw, 1);
    const float sc = 1.0f/2048.0f;
    #pragma unroll
    for (int j = 0; j < 4; j++) {
        int i = t + j*512;
        g_S[(size_t)row0*NG + i] = re[IX(i)]*sc;
        g_S[(size_t)row1*NG + i] = im[IX(i)]*sc;
    }
}

// ---------------------------------------------------------------- fp16 tensor-core MLP, g-tile 64
// half smem: SsmH [64][136] @0 (aliases: W2 chunk [128][40]; OsmF floats at buf)
//            HsmH [64][280] @17408B (alias during fc1 k-loop: W1 chunk [256][40])
#define SPADH 136
#define HPADH 280
#define WPADH 40
#define MLP_SMEM_BYTES (17408 + 64*HPADH*2)
__global__ void __launch_bounds__(256) k_mlp_tc(
        const float* __restrict__ x,
        const float* __restrict__ w1, const float* __restrict__ b1,
        const float* __restrict__ w2, const float* __restrict__ b2,
        float* __restrict__ out) {
    extern __shared__ char buf[];
    __half* SsmH  = (__half*)buf;            // [64][136]
    __half* HsmH  = (__half*)(buf + 17408);  // [64][280]
    __half* W1smH = HsmH;                    // alias fc1: [256][40]
    __half* W2smH = SsmH;                    // alias fc2: [128][40]
    float*  OsmF  = (float*)buf;             // [128][66] at epilogue

    int t = threadIdx.x;           // 256
    int lane = t & 31, w = t >> 5; // 8 warps
    int gid = lane >> 2, tig = lane & 3;
    int b = blockIdx.y, g0 = blockIdx.x * 64;

    // ---- load S tile transposed into SsmH[g][d] as fp16 ----
    {
        int d = t & 127, gq = t >> 7;
        const float* src = g_S + ((size_t)(b*ND + d))*NG + g0 + gq*32;
        #pragma unroll
        for (int j = 0; j < 8; j++) {
            float4 v = *(const float4*)(src + j*4);
            int gg = gq*32 + j*4;
            SsmH[(gg+0)*SPADH + d] = __float2half_rn(v.x);
            SsmH[(gg+1)*SPADH + d] = __float2half_rn(v.y);
            SsmH[(gg+2)*SPADH + d] = __float2half_rn(v.z);
            SsmH[(gg+3)*SPADH + d] = __float2half_rn(v.w);
        }
    }

    // ---- fc1: Ht[64g][256h], warp w owns h in [w*32, w*32+32) ----
    float acc1[4][4][4];
    #pragma unroll
    for (int i = 0; i < 4; i++)
        #pragma unroll
        for (int jn = 0; jn < 4; jn++)
            #pragma unroll
            for (int q = 0; q < 4; q++) acc1[i][jn][q] = 0.f;
    int n0w = w * 32;
    for (int kc = 0; kc < 4; kc++) {       // K=128 in chunks of 32
        __syncthreads();
        #pragma unroll
        for (int r = 0; r < 4; r++) {      // stage W1[256][32] -> W1smH[256][40]
            int h   = r*64 + (t >> 2);
            int seg = (t & 3) * 8;
            const float* wp = w1 + h*128 + kc*32 + seg;
            float4 v0 = *(const float4*)(wp);
            float4 v1 = *(const float4*)(wp + 4);
            __half2 h0 = __floats2half2_rn(v0.x, v0.y);
            __half2 h1 = __floats2half2_rn(v0.z, v0.w);
            __half2 h2 = __floats2half2_rn(v1.x, v1.y);
            __half2 h3 = __floats2half2_rn(v1.z, v1.w);
            uint4 u = make_uint4(h2u(h0), h2u(h1), h2u(h2), h2u(h3));
            *(uint4*)(W1smH + h*WPADH + seg) = u;
        }
        __syncthreads();
        #pragma unroll
        for (int ks = 0; ks < 2; ks++) {
            int ka = kc*32 + ks*16 + 2*tig;
            unsigned af[4][4];
            #pragma unroll
            for (int i = 0; i < 4; i++) {
                const __half* Ar = SsmH + (i*16 + gid)*SPADH + ka;
                af[i][0] = *(const unsigned*)(Ar);
                af[i][1] = *(const unsigned*)(Ar + 8*SPADH);
                af[i][2] = *(const unsigned*)(Ar + 8);
                af[i][3] = *(const unsigned*)(Ar + 8*SPADH + 8);
            }
            int kb = ks*16 + 2*tig;
            #pragma unroll
            for (int jn = 0; jn < 4; jn++) {
                int h = n0w + jn*8 + gid;
                unsigned b0 = *(const unsigned*)(W1smH + h*WPADH + kb);
                unsigned b1 = *(const unsigned*)(W1smH + h*WPADH + kb + 8);
                #pragma unroll
                for (int i = 0; i < 4; i++) mma16h(acc1[i][jn], af[i], b0, b1);
            }
        }
    }
    __syncthreads();   // done with W1smH -> becomes HsmH
    // bias + GELU -> HsmH[g][h] (half2 stores)
    #pragma unroll
    for (int jn = 0; jn < 4; jn++) {
        int n0 = n0w + jn*8;
        float bb0 = b1[n0 + 2*tig];
        float bb1 = b1[n0 + 2*tig + 1];
        #pragma unroll
        for (int i = 0; i < 4; i++) {
            int r0 = i*16 + gid;
            float g00 = gelu_exact(acc1[i][jn][0] + bb0);
            float g01 = gelu_exact(acc1[i][jn][1] + bb1);
            float g10 = gelu_exact(acc1[i][jn][2] + bb0);
            float g11 = gelu_exact(acc1[i][jn][3] + bb1);
            *(__half2*)(HsmH + r0*HPADH     + n0 + 2*tig) = __floats2half2_rn(g00, g01);
            *(__half2*)(HsmH + (r0+8)*HPADH + n0 + 2*tig) = __floats2half2_rn(g10, g11);
        }
    }

    // ---- fc2: outT[64g][128d], warp w owns d in [w*16, w*16+16) ----
    float acc2[4][2][4];
    #pragma unroll
    for (int i = 0; i < 4; i++)
        #pragma unroll
        for (int jn = 0; jn < 2; jn++)
            #pragma unroll
            for (int q = 0; q < 4; q++) acc2[i][jn][q] = 0.f;
    int n0w2 = w * 16;
    for (int kc = 0; kc < 8; kc++) {       // K=256 in chunks of 32
        __syncthreads();
        #pragma unroll
        for (int r = 0; r < 2; r++) {      // stage W2[128][32] -> W2smH[128][40]
            int d   = r*64 + (t >> 2);
            int seg = (t & 3) * 8;
            const float* wp = w2 + d*256 + kc*32 + seg;
            float4 v0 = *(const float4*)(wp);
            float4 v1 = *(const float4*)(wp + 4);
            __half2 h0 = __floats2half2_rn(v0.x, v0.y);
            __half2 h1 = __floats2half2_rn(v0.z, v0.w);
            __half2 h2 = __floats2half2_rn(v1.x, v1.y);
            __half2 h3 = __floats2half2_rn(v1.z, v1.w);
            uint4 u = make_uint4(h2u(h0), h2u(h1), h2u(h2), h2u(h3));
            *(uint4*)(W2smH + d*WPADH + seg) = u;
        }
        __syncthreads();
        #pragma unroll
        for (int ks = 0; ks < 2; ks++) {
            int ka = kc*32 + ks*16 + 2*tig;
            unsigned af[4][4];
            #pragma unroll
            for (int i = 0; i < 4; i++) {
                const __half* Ar = HsmH + (i*16 + gid)*HPADH + ka;
                af[i][0] = *(const unsigned*)(Ar);
                af[i][1] = *(const unsigned*)(Ar + 8*HPADH);
                af[i][2] = *(const unsigned*)(Ar + 8);
                af[i][3] = *(const unsigned*)(Ar + 8*HPADH + 8);
            }
            int kb = ks*16 + 2*tig;
            #pragma unroll
            for (int jn = 0; jn < 2; jn++) {
                int d = n0w2 + jn*8 + gid;
                unsigned b0 = *(const unsigned*)(W2smH + d*WPADH + kb);
                unsigned b1 = *(const unsigned*)(W2smH + d*WPADH + kb + 8);
                #pragma unroll
                for (int i = 0; i < 4; i++) mma16h(acc2[i][jn], af[i], b0, b1);
            }
        }
    }
    __syncthreads();   // weights/H consumed -> OsmF
    // transpose through OsmF[d][g]  (stride 66)
    #pragma unroll
    for (int jn = 0; jn < 2; jn++) {
        int n0 = n0w2 + jn*8;
        #pragma unroll
        for (int i = 0; i < 4; i++) {
            int r0 = i*16 + gid;
            OsmF[(n0+2*tig)*66   + r0]   = acc2[i][jn][0];
            OsmF[(n0+2*tig+1)*66 + r0]   = acc2[i][jn][1];
            OsmF[(n0+2*tig)*66   + r0+8] = acc2[i][jn][2];
            OsmF[(n0+2*tig+1)*66 + r0+8] = acc2[i][jn][3];
        }
    }
    __syncthreads();
    // final: out = x + outT^T + b2 (coalesced float4 along g)
    {
        int d = t >> 1, gh = t & 1;
        float bias = b2[d];
        size_t obase = ((size_t)(b*ND + d))*NG + g0 + gh*32;
        const float* orow = OsmF + d*66 + gh*32;
        #pragma unroll
        for (int j = 0; j < 8; j++) {
            float4 xv = *(const float4*)(x + obase + j*4);
            float4 res;
            res.x = xv.x + orow[j*4]     + bias;
            res.y = xv.y + orow[j*4 + 1] + bias;
            res.z = xv.z + orow[j*4 + 2] + bias;
            res.w = xv.w + orow[j*4 + 3] + bias;
            *(float4*)(out + obase + j*4) = res;
        }
    }
}

// ----------------------------------------------------------------
extern "C" void kernel_launch(void* const* d_in, const int* in_sizes, int n_in,
                              void* d_out, int out_size) {
    const float* x     = (const float*)d_in[0];
    const float* Phi   = (const float*)d_in[1];
    const float* Theta = (const float*)d_in[2];
    const float* gam   = (const float*)d_in[3];
    const float* bet   = (const float*)d_in[4];
    const float* w1    = (const float*)d_in[5];
    const float* b1    = (const float*)d_in[6];
    const float* w2    = (const float*)d_in[7];
    const float* b2    = (const float*)d_in[8];
    float* out = (float*)d_out;

    cudaFuncSetAttribute(k_mlp_tc, cudaFuncAttributeMaxDynamicSharedMemorySize, MLP_SMEM_BYTES);

    k_lnstats<<<dim3(16, 8), 512>>>(x);
    k_build_M<<<dim3(64, 33), 256>>>(Phi, Theta);
    k_fft_fwd<<<512, 512>>>(x, gam, bet);
    k_sf_mma<<<NGF, 256>>>();
    k_ifft<<<512, 512>>>();
    k_mlp_tc<<<dim3(NG/64, NB), 256, MLP_SMEM_BYTES>>>(x, w1, b1, w2, b2, out);
}

// round 14
// speedup vs baseline: 4.6698x; 1.0239x over previous
#include <cuda_runtime.h>
#include <cuda_fp16.h>
#include <math.h>

#define NB 8
#define ND 128
#define NG 2048
#define NL 24
#define NGF 1025
#define NDD 16384   // D*D

// swizzled smem index for FFT: kills bit-reversal bank conflicts
#define IX(i) ((i) + ((i) >> 5))

// Scratch (device globals: allocation-free contract)
__device__ float  g_mean[NB*NG];
__device__ float  g_rstd[NB*NG];
__device__ float2 g_Xf[NGF*NB*ND];            // [f][row = b*128+d]
__device__ __half g_Mh[(size_t)NGF*NDD];      // [f][h][d]  33.6 MB (fp16)
__device__ float2 g_Sf[(size_t)NGF*NB*ND];    // [f][row = b*128+h]  (transposed layout)
__device__ __half g_Sh[(size_t)NB*ND*NG];     // [row][g]  fp16 (16.8 MB)

// ---------------------------------------------------------------- mma helpers
__device__ __forceinline__ void mma16h(float* c, const unsigned* a, unsigned b0, unsigned b1) {
    asm volatile("mma.sync.aligned.m16n8k16.row.col.f32.f16.f16.f32 "
        "{%0,%1,%2,%3},{%4,%5,%6,%7},{%8,%9},{%0,%1,%2,%3};"
        : "+f"(c[0]), "+f"(c[1]), "+f"(c[2]), "+f"(c[3])
        : "r"(a[0]), "r"(a[1]), "r"(a[2]), "r"(a[3]), "r"(b0), "r"(b1));
}
__device__ __forceinline__ float gelu_exact(float v) {
    return 0.5f*v*(1.f + erff(v*0.70710678118654752f));
}
__device__ __forceinline__ unsigned h2u(__half2 h) { return *(unsigned*)&h; }

// ---------------------------------------------------------------- LN stats (4-way d split)
__global__ void k_lnstats(const float* __restrict__ x) {
    __shared__ float ps[4*128], pss[4*128];
    int t = threadIdx.x;               // 512
    int g = t & 127, dq = t >> 7;      // dq 0..3
    int b = blockIdx.y;
    int g0 = blockIdx.x * 128;
    const float* p = x + (size_t)b*ND*NG + (size_t)(dq*32)*NG + g0 + g;
    float s = 0.f, ss = 0.f;
    #pragma unroll 8
    for (int d = 0; d < 32; d++) { float v = p[(size_t)d*NG]; s += v; ss += v*v; }
    ps[dq*128+g] = s; pss[dq*128+g] = ss;
    __syncthreads();
    if (dq == 0) {
        float S  = ps[g]  + ps[128+g]  + ps[256+g]  + ps[384+g];
        float SS = pss[g] + pss[128+g] + pss[256+g] + pss[384+g];
        float mean = S * (1.f/ND);
        float var  = SS * (1.f/ND) - mean*mean;
        g_mean[b*NG + g0 + g] = mean;
        g_rstd[b*NG + g0 + g] = rsqrtf(var + 1e-5f);
    }
}

// ---------------------------------------------------------------- radix-4 fused FFT 2048 (512 threads)
__device__ __forceinline__ void fft2048_r4(float* re, float* im, const float2* tw, int inv) {
    int t = threadIdx.x;   // 512
    __syncthreads();
    #pragma unroll
    for (int j = 0; j < 2; j++) {
        int k = t + j*512;
        int i0 = IX(2*k), i1 = IX(2*k+1);
        float ar = re[i0], ai = im[i0], br = re[i1], bi = im[i1];
        re[i0] = ar+br; im[i0] = ai+bi;
        re[i1] = ar-br; im[i1] = ai-bi;
    }
    #pragma unroll
    for (int s = 0; s < 5; s++) {
        int lq = 2*s + 1;
        int q  = 1 << lq;
        __syncthreads();
        int pos = t & (q-1);
        int i0l = ((t >> lq) << (lq+2)) + pos;
        int i0 = IX(i0l), i1 = IX(i0l+q), i2 = IX(i0l+2*q), i3 = IX(i0l+3*q);
        float2 w1 = tw[pos << (10-lq)];
        float2 w2 = tw[pos << (9-lq)];
        if (inv) { w1.y = -w1.y; w2.y = -w2.y; }
        float w3x = inv ? -w2.y : w2.y;
        float w3y = inv ?  w2.x : -w2.x;
        float x0r=re[i0], x0i=im[i0];
        float x1r=re[i1], x1i=im[i1];
        float x2r=re[i2], x2i=im[i2];
        float x3r=re[i3], x3i=im[i3];
        float a1r = w1.x*x1r - w1.y*x1i, a1i = w1.x*x1i + w1.y*x1r;
        float a3r = w1.x*x3r - w1.y*x3i, a3i = w1.x*x3i + w1.y*x3r;
        float u0r = x0r+a1r, u0i = x0i+a1i;
        float u1r = x0r-a1r, u1i = x0i-a1i;
        float u2r = x2r+a3r, u2i = x2i+a3i;
        float u3r = x2r-a3r, u3i = x2i-a3i;
        float b2r = w2.x*u2r - w2.y*u2i, b2i = w2.x*u2i + w2.y*u2r;
        float b3r = w3x*u3r - w3y*u3i,  b3i = w3x*u3i + w3y*u3r;
        re[i0]=u0r+b2r; im[i0]=u0i+b2i;
        re[i2]=u0r-b2r; im[i2]=u0i-b2i;
        re[i1]=u1r+b3r; im[i1]=u1i+b3i;
        re[i3]=u1r-b3r; im[i3]=u1i-b3i;
    }
    __syncthreads();
}

// ---------------------------------------------------------------- LN-apply + packed real FFT
__global__ void k_fft_fwd(const float* __restrict__ x,
                          const float* __restrict__ gamma,
                          const float* __restrict__ beta) {
    __shared__ float re[2112], im[2112];
    __shared__ float2 tw[1024];
    int t = threadIdx.x;   // 512
    int row0 = blockIdx.x*2, row1 = row0 + 1;
    int b = row0 >> 7;
    int d0 = row0 & 127, d1 = d0 + 1;
    for (int j = t; j < 1024; j += 512) {
        float sv, cv;
        __sincosf(-6.2831853071795864769f * (float)j * (1.f/2048.f), &sv, &cv);
        tw[j] = make_float2(cv, sv);
    }
    const float* xp0 = x + (size_t)row0*NG;
    const float* xp1 = x + (size_t)row1*NG;
    const float* mp  = g_mean + b*NG;
    const float* rp  = g_rstd + b*NG;
    float ga0 = gamma[d0], be0 = beta[d0], ga1 = gamma[d1], be1 = beta[d1];
    #pragma unroll
    for (int j = 0; j < 4; j++) {
        int i = t + j*512;
        float m = mp[i], r = rp[i];
        float z0 = (xp0[i]-m)*r*ga0 + be0;
        float z1 = (xp1[i]-m)*r*ga1 + be1;
        int rv = __brev(i) >> 21;
        re[IX(rv)] = z0; im[IX(rv)] = z1;
    }
    fft2048_r4(re, im, tw, 0);
    // unpack two real spectra; rows adjacent in [f][row] layout -> one float4 store
    for (int k = t; k <= 1024; k += 512) {
        int km = (2048 - k) & 2047;
        float zr = re[IX(k)],  zi = im[IX(k)];
        float mr = re[IX(km)], mi = im[IX(km)];
        float4 AB = make_float4(0.5f*(zr+mr), 0.5f*(zi-mi),     // row0 spectrum
                                0.5f*(zi+mi), 0.5f*(mr-zr));    // row1 spectrum
        *(float4*)(&g_Xf[(size_t)k*(NB*ND) + row0]) = AB;       // row0 even -> 16B aligned
    }
}

// ---------------------------------------------------------------- M[f,h,d] = sum_l Phi[l,f]*Theta[l,h,d]  (fp16 out)
__global__ void k_build_M(const float* __restrict__ Phi, const float* __restrict__ Theta) {
    __shared__ float sphi[NL*32];
    int t  = threadIdx.x;
    int i  = blockIdx.x*256 + t;      // h*128+d
    int f0 = blockIdx.y*32;
    for (int idx = t; idx < NL*32; idx += 256) {
        int l = idx >> 5, ff = idx & 31;
        sphi[idx] = (f0+ff < NGF) ? Phi[l*NGF + f0 + ff] : 0.f;
    }
    __syncthreads();
    float th[NL];
    #pragma unroll
    for (int l = 0; l < NL; l++) th[l] = Theta[l*NDD + i];
    float4 acc[8];
    #pragma unroll
    for (int j = 0; j < 8; j++) acc[j] = make_float4(0.f,0.f,0.f,0.f);
    #pragma unroll
    for (int l = 0; l < NL; l++) {
        const float4* sp = (const float4*)(sphi + l*32);
        float tl = th[l];
        #pragma unroll
        for (int j = 0; j < 8; j++) {
            float4 p = sp[j];
            acc[j].x += p.x*tl; acc[j].y += p.y*tl;
            acc[j].z += p.z*tl; acc[j].w += p.w*tl;
        }
    }
    #pragma unroll
    for (int j = 0; j < 8; j++) {
        float v[4] = {acc[j].x, acc[j].y, acc[j].z, acc[j].w};
        #pragma unroll
        for (int c = 0; c < 4; c++) {
            int ff = f0 + j*4 + c;
            if (ff < NGF) g_Mh[(size_t)ff*NDD + i] = __float2half_rn(v[c]);
        }
    }
}

// ---------------------------------------------------------------- S_f: tensor-core (round-8 core, coalesced [f][row] stores)
// Per block: one f. C[128h x 16n] = M[f](128h x 128d, fp16) * X(128d x 16n, fp16)
// n = 2*b + (0:re, 1:im). fp32 accumulate. 8 warps, warp w owns h in [16w, 16w+16).
#define MPAD 136   // halves per smem row (272B: conflict-free frag loads)
__global__ void __launch_bounds__(256) k_sf_mma() {
    __shared__ __half Msm[128*MPAD];   // 34816 B
    __shared__ __half Xsm[16*MPAD];    // 4352 B
    int t = threadIdx.x;       // 256
    int f = blockIdx.x;

    // stage M via cp.async: 128 rows x 16 chunks of 16B
    {
        const char* src = (const char*)(g_Mh + (size_t)f*NDD);
        unsigned sbase = (unsigned)__cvta_generic_to_shared(Msm);
        #pragma unroll
        for (int j = 0; j < 8; j++) {
            int idx = t + j*256;        // 0..2047
            int row = idx >> 4, c = idx & 15;
            unsigned dst = sbase + row*(MPAD*2) + c*16;
            asm volatile("cp.async.cg.shared.global [%0], [%1], 16;"
                         :: "r"(dst), "l"(src + row*256 + c*16));
        }
        asm volatile("cp.async.commit_group;");
    }
    // stage X transposed (fp32 -> fp16): Xsm[n = 2b+reim][d]
    #pragma unroll
    for (int j = 0; j < 4; j++) {
        int idx = t + j*256;            // b*128 + d
        float2 v = g_Xf[(size_t)f*1024 + idx];
        int b = idx >> 7, d = idx & 127;
        Xsm[(2*b)*MPAD + d]   = __float2half_rn(v.x);
        Xsm[(2*b+1)*MPAD + d] = __float2half_rn(v.y);
    }
    asm volatile("cp.async.wait_group 0;");
    __syncthreads();

    int lane = t & 31, w = t >> 5;
    int gid = lane >> 2, tig = lane & 3;
    int h0 = w * 16;
    float c[2][4];
    #pragma unroll
    for (int j = 0; j < 2; j++)
        #pragma unroll
        for (int q = 0; q < 4; q++) c[j][q] = 0.f;

    const __half* Arow0 = Msm + (h0 + gid)*MPAD;
    const __half* Arow1 = Msm + (h0 + gid + 8)*MPAD;
    #pragma unroll
    for (int kc = 0; kc < 8; kc++) {
        int k0 = kc*16 + 2*tig;
        unsigned a[4];
        a[0] = *(const unsigned*)(Arow0 + k0);
        a[1] = *(const unsigned*)(Arow1 + k0);
        a[2] = *(const unsigned*)(Arow0 + k0 + 8);
        a[3] = *(const unsigned*)(Arow1 + k0 + 8);
        #pragma unroll
        for (int j = 0; j < 2; j++) {
            int n = j*8 + gid;
            unsigned b0 = *(const unsigned*)(Xsm + n*MPAD + k0);
            unsigned b1 = *(const unsigned*)(Xsm + n*MPAD + k0 + 8);
            mma16h(c[j], a, b0, b1);
        }
    }
    // store to g_Sf[f][row]: 8 consecutive h per (tig,j) group -> 64B runs, coalesced
    {
        float2* dst = g_Sf + (size_t)f*1024;
        #pragma unroll
        for (int j = 0; j < 2; j++) {
            int b = 4*j + tig;
            int h_lo = h0 + gid, h_hi = h_lo + 8;
            dst[b*ND + h_lo] = make_float2(c[j][0], c[j][1]);
            dst[b*ND + h_hi] = make_float2(c[j][2], c[j][3]);
        }
    }
}

// ---------------------------------------------------------------- packed irfft (reads [f][row] Sf, writes fp16 S)
__global__ void k_ifft() {
    __shared__ float re[2112], im[2112];
    __shared__ float2 tw[1024];
    int t = threadIdx.x;   // 512
    int row0 = blockIdx.x*2, row1 = row0 + 1;
    for (int j = t; j < 1024; j += 512) {
        float sv, cv;
        __sincosf(-6.2831853071795864769f * (float)j * (1.f/2048.f), &sv, &cv);
        tw[j] = make_float2(cv, sv);
    }
    #pragma unroll
    for (int j = 0; j < 4; j++) {
        int i = t + j*512;
        int src = (i <= 1024) ? i : 2048 - i;
        // rows adjacent in [f][row] layout; row0 even -> aligned float4
        float4 vv = *(const float4*)(&g_Sf[(size_t)src*1024 + row0]);
        float2 v0 = make_float2(vv.x, vv.y);
        float2 v1 = make_float2(vv.z, vv.w);
        if (i > 1024) { v0.y = -v0.y; v1.y = -v1.y; }
        int rv = __brev(i) >> 21;
        re[IX(rv)] = v0.x - v1.y;
        im[IX(rv)] = v0.y + v1.x;
    }
    fft2048_r4(re, im, tw, 1);
    const float sc = 1.0f/2048.0f;
    #pragma unroll
    for (int j = 0; j < 4; j++) {
        int i = t + j*512;
        g_Sh[(size_t)row0*NG + i] = __float2half_rn(re[IX(i)]*sc);
        g_Sh[(size_t)row1*NG + i] = __float2half_rn(im[IX(i)]*sc);
    }
}

// ---------------------------------------------------------------- fp16 tensor-core MLP, g-tile 64
// half smem: SsmH [64][136] @0 (aliases: W2 chunk [128][40]; OsmF floats at buf)
//            HsmH [64][280] @17408B (alias during fc1 k-loop: W1 chunk [256][40])
#define SPADH 136
#define HPADH 280
#define WPADH 40
#define MLP_SMEM_BYTES (17408 + 64*HPADH*2)
__global__ void __launch_bounds__(256) k_mlp_tc(
        const float* __restrict__ x,
        const float* __restrict__ w1, const float* __restrict__ b1,
        const float* __restrict__ w2, const float* __restrict__ b2,
        float* __restrict__ out) {
    extern __shared__ char buf[];
    __half* SsmH  = (__half*)buf;            // [64][136]
    __half* HsmH  = (__half*)(buf + 17408);  // [64][280]
    __half* W1smH = HsmH;                    // alias fc1: [256][40]
    __half* W2smH = SsmH;                    // alias fc2: [128][40]
    float*  OsmF  = (float*)buf;             // [128][66] at epilogue

    int t = threadIdx.x;           // 256
    int lane = t & 31, w = t >> 5; // 8 warps
    int gid = lane >> 2, tig = lane & 3;
    int b = blockIdx.y, g0 = blockIdx.x * 64;

    // ---- load S tile (already fp16) transposed into SsmH[g][d] ----
    {
        int d = t & 127, gq = t >> 7;
        const __half* src = g_Sh + ((size_t)(b*ND + d))*NG + g0 + gq*32;
        #pragma unroll
        for (int j = 0; j < 4; j++) {
            uint4 u = *(const uint4*)(src + j*8);
            __half2 p0 = *(__half2*)&u.x, p1 = *(__half2*)&u.y;
            __half2 p2 = *(__half2*)&u.z, p3 = *(__half2*)&u.w;
            int gg = gq*32 + j*8;
            SsmH[(gg+0)*SPADH + d] = __low2half(p0);
            SsmH[(gg+1)*SPADH + d] = __high2half(p0);
            SsmH[(gg+2)*SPADH + d] = __low2half(p1);
            SsmH[(gg+3)*SPADH + d] = __high2half(p1);
            SsmH[(gg+4)*SPADH + d] = __low2half(p2);
            SsmH[(gg+5)*SPADH + d] = __high2half(p2);
            SsmH[(gg+6)*SPADH + d] = __low2half(p3);
            SsmH[(gg+7)*SPADH + d] = __high2half(p3);
        }
    }

    // ---- fc1: Ht[64g][256h], warp w owns h in [w*32, w*32+32) ----
    float acc1[4][4][4];
    #pragma unroll
    for (int i = 0; i < 4; i++)
        #pragma unroll
        for (int jn = 0; jn < 4; jn++)
            #pragma unroll
            for (int q = 0; q < 4; q++) acc1[i][jn][q] = 0.f;
    int n0w = w * 32;
    for (int kc = 0; kc < 4; kc++) {       // K=128 in chunks of 32
        __syncthreads();
        #pragma unroll
        for (int r = 0; r < 4; r++) {      // stage W1[256][32] -> W1smH[256][40]
            int h   = r*64 + (t >> 2);
            int seg = (t & 3) * 8;
            const float* wp = w1 + h*128 + kc*32 + seg;
            float4 v0 = *(const float4*)(wp);
            float4 v1 = *(const float4*)(wp + 4);
            __half2 h0 = __floats2half2_rn(v0.x, v0.y);
            __half2 h1 = __floats2half2_rn(v0.z, v0.w);
            __half2 h2 = __floats2half2_rn(v1.x, v1.y);
            __half2 h3 = __floats2half2_rn(v1.z, v1.w);
            uint4 u = make_uint4(h2u(h0), h2u(h1), h2u(h2), h2u(h3));
            *(uint4*)(W1smH + h*WPADH + seg) = u;
        }
        __syncthreads();
        #pragma unroll
        for (int ks = 0; ks < 2; ks++) {
            int ka = kc*32 + ks*16 + 2*tig;
            unsigned af[4][4];
            #pragma unroll
            for (int i = 0; i < 4; i++) {
                const __half* Ar = SsmH + (i*16 + gid)*SPADH + ka;
                af[i][0] = *(const unsigned*)(Ar);
                af[i][1] = *(const unsigned*)(Ar + 8*SPADH);
                af[i][2] = *(const unsigned*)(Ar + 8);
                af[i][3] = *(const unsigned*)(Ar + 8*SPADH + 8);
            }
            int kb = ks*16 + 2*tig;
            #pragma unroll
            for (int jn = 0; jn < 4; jn++) {
                int h = n0w + jn*8 + gid;
                unsigned b0 = *(const unsigned*)(W1smH + h*WPADH + kb);
                unsigned b1 = *(const unsigned*)(W1smH + h*WPADH + kb + 8);
                #pragma unroll
                for (int i = 0; i < 4; i++) mma16h(acc1[i][jn], af[i], b0, b1);
            }
        }
    }
    __syncthreads();   // done with W1smH -> becomes HsmH
    // bias + GELU -> HsmH[g][h] (half2 stores)
    #pragma unroll
    for (int jn = 0; jn < 4; jn++) {
        int n0 = n0w + jn*8;
        float bb0 = b1[n0 + 2*tig];
        float bb1 = b1[n0 + 2*tig + 1];
        #pragma unroll
        for (int i = 0; i < 4; i++) {
            int r0 = i*16 + gid;
            float g00 = gelu_exact(acc1[i][jn][0] + bb0);
            float g01 = gelu_exact(acc1[i][jn][1] + bb1);
            float g10 = gelu_exact(acc1[i][jn][2] + bb0);
            float g11 = gelu_exact(acc1[i][jn][3] + bb1);
            *(__half2*)(HsmH + r0*HPADH     + n0 + 2*tig) = __floats2half2_rn(g00, g01);
            *(__half2*)(HsmH + (r0+8)*HPADH + n0 + 2*tig) = __floats2half2_rn(g10, g11);
        }
    }

    // ---- fc2: outT[64g][128d], warp w owns d in [w*16, w*16+16) ----
    float acc2[4][2][4];
    #pragma unroll
    for (int i = 0; i < 4; i++)
        #pragma unroll
        for (int jn = 0; jn < 2; jn++)
            #pragma unroll
            for (int q = 0; q < 4; q++) acc2[i][jn][q] = 0.f;
    int n0w2 = w * 16;
    for (int kc = 0; kc < 8; kc++) {       // K=256 in chunks of 32
        __syncthreads();
        #pragma unroll
        for (int r = 0; r < 2; r++) {      // stage W2[128][32] -> W2smH[128][40]
            int d   = r*64 + (t >> 2);
            int seg = (t & 3) * 8;
            const float* wp = w2 + d*256 + kc*32 + seg;
            float4 v0 = *(const float4*)(wp);
            float4 v1 = *(const float4*)(wp + 4);
            __half2 h0 = __floats2half2_rn(v0.x, v0.y);
            __half2 h1 = __floats2half2_rn(v0.z, v0.w);
            __half2 h2 = __floats2half2_rn(v1.x, v1.y);
            __half2 h3 = __floats2half2_rn(v1.z, v1.w);
            uint4 u = make_uint4(h2u(h0), h2u(h1), h2u(h2), h2u(h3));
            *(uint4*)(W2smH + d*WPADH + seg) = u;
        }
        __syncthreads();
        #pragma unroll
        for (int ks = 0; ks < 2; ks++) {
            int ka = kc*32 + ks*16 + 2*tig;
            unsigned af[4][4];
            #pragma unroll
            for (int i = 0; i < 4; i++) {
                const __half* Ar = HsmH + (i*16 + gid)*HPADH + ka;
                af[i][0] = *(const unsigned*)(Ar);
                af[i][1] = *(const unsigned*)(Ar + 8*HPADH);
                af[i][2] = *(const unsigned*)(Ar + 8);
                af[i][3] = *(const unsigned*)(Ar + 8*HPADH + 8);
            }
            int kb = ks*16 + 2*tig;
            #pragma unroll
            for (int jn = 0; jn < 2; jn++) {
                int d = n0w2 + jn*8 + gid;
                unsigned b0 = *(const unsigned*)(W2smH + d*WPADH + kb);
                unsigned b1 = *(const unsigned*)(W2smH + d*WPADH + kb + 8);
                #pragma unroll
                for (int i = 0; i < 4; i++) mma16h(acc2[i][jn], af[i], b0, b1);
            }
        }
    }
    __syncthreads();   // weights/H consumed -> OsmF
    // transpose through OsmF[d][g]  (stride 66)
    #pragma unroll
    for (int jn = 0; jn < 2; jn++) {
        int n0 = n0w2 + jn*8;
        #pragma unroll
        for (int i = 0; i < 4; i++) {
            int r0 = i*16 + gid;
            OsmF[(n0+2*tig)*66   + r0]   = acc2[i][jn][0];
            OsmF[(n0+2*tig+1)*66 + r0]   = acc2[i][jn][1];
            OsmF[(n0+2*tig)*66   + r0+8] = acc2[i][jn][2];
            OsmF[(n0+2*tig+1)*66 + r0+8] = acc2[i][jn][3];
        }
    }
    __syncthreads();
    // final: out = x + outT^T + b2 (coalesced float4 along g)
    {
        int d = t >> 1, gh = t & 1;
        float bias = b2[d];
        size_t obase = ((size_t)(b*ND + d))*NG + g0 + gh*32;
        const float* orow = OsmF + d*66 + gh*32;
        #pragma unroll
        for (int j = 0; j < 8; j++) {
            float4 xv = *(const float4*)(x + obase + j*4);
            float4 res;
            res.x = xv.x + orow[j*4]     + bias;
            res.y = xv.y + orow[j*4 + 1] + bias;
            res.z = xv.z + orow[j*4 + 2] + bias;
            res.w = xv.w + orow[j*4 + 3] + bias;
            *(float4*)(out + obase + j*4) = res;
        }
    }
}

// ----------------------------------------------------------------
extern "C" void kernel_launch(void* const* d_in, const int* in_sizes, int n_in,
                              void* d_out, int out_size) {
    const float* x     = (const float*)d_in[0];
    const float* Phi   = (const float*)d_in[1];
    const float* Theta = (const float*)d_in[2];
    const float* gam   = (const float*)d_in[3];
    const float* bet   = (const float*)d_in[4];
    const float* w1    = (const float*)d_in[5];
    const float* b1    = (const float*)d_in[6];
    const float* w2    = (const float*)d_in[7];
    const float* b2    = (const float*)d_in[8];
    float* out = (float*)d_out;

    cudaFuncSetAttribute(k_mlp_tc, cudaFuncAttributeMaxDynamicSharedMemorySize, MLP_SMEM_BYTES);

    k_lnstats<<<dim3(16, 8), 512>>>(x);
    k_build_M<<<dim3(64, 33), 256>>>(Phi, Theta);
    k_fft_fwd<<<512, 512>>>(x, gam, bet);
    k_sf_mma<<<NGF, 256>>>();
    k_ifft<<<512, 512>>>();
    k_mlp_tc<<<dim3(NG/64, NB), 256, MLP_SMEM_BYTES>>>(x, w1, b1, w2, b2, out);
}

// round 15
// speedup vs baseline: 4.8740x; 1.0437x over previous
#include <cuda_runtime.h>
#include <cuda_fp16.h>
#include <math.h>

#define NB 8
#define ND 128
#define NG 2048
#define NL 24
#define NGF 1025
#define NDD 16384   // D*D

// swizzled smem index for FFT: kills bit-reversal bank conflicts
#define IX(i) ((i) + ((i) >> 5))

// Scratch (device globals: allocation-free contract)
__device__ float  g_mean[NB*NG];
__device__ float  g_rstd[NB*NG];
__device__ float2 g_Xf[NGF*NB*ND];            // [f][row = b*128+d]
__device__ __half g_Mh[(size_t)NGF*NDD];      // [f][h][d]  33.6 MB (fp16)
__device__ float2 g_Sf[(size_t)NGF*NB*ND];    // [f][row = b*128+h]
__device__ __half g_Sh[(size_t)NB*ND*NG];     // [row][g]  fp16
__device__ __half g_w1h[256*128];             // fp16 weights (pre-converted)
__device__ __half g_w2h[128*256];

// ---------------------------------------------------------------- mma helpers
__device__ __forceinline__ void mma16h(float* c, const unsigned* a, unsigned b0, unsigned b1) {
    asm volatile("mma.sync.aligned.m16n8k16.row.col.f32.f16.f16.f32 "
        "{%0,%1,%2,%3},{%4,%5,%6,%7},{%8,%9},{%0,%1,%2,%3};"
        : "+f"(c[0]), "+f"(c[1]), "+f"(c[2]), "+f"(c[3])
        : "r"(a[0]), "r"(a[1]), "r"(a[2]), "r"(a[3]), "r"(b0), "r"(b1));
}
__device__ __forceinline__ float gelu_exact(float v) {
    return 0.5f*v*(1.f + erff(v*0.70710678118654752f));
}

// ---------------------------------------------------------------- weight pre-conversion (once)
__global__ void k_cvt_w(const float* __restrict__ w1, const float* __restrict__ w2) {
    int i = blockIdx.x*256 + threadIdx.x;    // 128 blocks -> 32768 threads
    g_w1h[i] = __float2half_rn(w1[i]);
    g_w2h[i] = __float2half_rn(w2[i]);
}

// ---------------------------------------------------------------- LN stats (8-way d split, 256 blocks)
__global__ void k_lnstats(const float* __restrict__ x) {
    __shared__ float ps[8*64], pss[8*64];
    int t = threadIdx.x;               // 512
    int g = t & 63, dq = t >> 6;       // dq 0..7
    int b = blockIdx.y;
    int g0 = blockIdx.x * 64;          // grid.x = 32
    const float* p = x + (size_t)b*ND*NG + (size_t)(dq*16)*NG + g0 + g;
    float s = 0.f, ss = 0.f;
    #pragma unroll 16
    for (int d = 0; d < 16; d++) { float v = p[(size_t)d*NG]; s += v; ss += v*v; }
    ps[dq*64+g] = s; pss[dq*64+g] = ss;
    __syncthreads();
    if (dq == 0) {
        float S = 0.f, SS = 0.f;
        #pragma unroll
        for (int k = 0; k < 8; k++) { S += ps[k*64+g]; SS += pss[k*64+g]; }
        float mean = S * (1.f/ND);
        float var  = SS * (1.f/ND) - mean*mean;
        g_mean[b*NG + g0 + g] = mean;
        g_rstd[b*NG + g0 + g] = rsqrtf(var + 1e-5f);
    }
}

// ---------------------------------------------------------------- radix-4 fused FFT 2048 (512 threads)
__device__ __forceinline__ void fft2048_r4(float* re, float* im, const float2* tw, int inv) {
    int t = threadIdx.x;   // 512
    __syncthreads();
    #pragma unroll
    for (int j = 0; j < 2; j++) {
        int k = t + j*512;
        int i0 = IX(2*k), i1 = IX(2*k+1);
        float ar = re[i0], ai = im[i0], br = re[i1], bi = im[i1];
        re[i0] = ar+br; im[i0] = ai+bi;
        re[i1] = ar-br; im[i1] = ai-bi;
    }
    #pragma unroll
    for (int s = 0; s < 5; s++) {
        int lq = 2*s + 1;
        int q  = 1 << lq;
        __syncthreads();
        int pos = t & (q-1);
        int i0l = ((t >> lq) << (lq+2)) + pos;
        int i0 = IX(i0l), i1 = IX(i0l+q), i2 = IX(i0l+2*q), i3 = IX(i0l+3*q);
        float2 w1 = tw[pos << (10-lq)];
        float2 w2 = tw[pos << (9-lq)];
        if (inv) { w1.y = -w1.y; w2.y = -w2.y; }
        float w3x = inv ? -w2.y : w2.y;
        float w3y = inv ?  w2.x : -w2.x;
        float x0r=re[i0], x0i=im[i0];
        float x1r=re[i1], x1i=im[i1];
        float x2r=re[i2], x2i=im[i2];
        float x3r=re[i3], x3i=im[i3];
        float a1r = w1.x*x1r - w1.y*x1i, a1i = w1.x*x1i + w1.y*x1r;
        float a3r = w1.x*x3r - w1.y*x3i, a3i = w1.x*x3i + w1.y*x3r;
        float u0r = x0r+a1r, u0i = x0i+a1i;
        float u1r = x0r-a1r, u1i = x0i-a1i;
        float u2r = x2r+a3r, u2i = x2i+a3i;
        float u3r = x2r-a3r, u3i = x2i-a3i;
        float b2r = w2.x*u2r - w2.y*u2i, b2i = w2.x*u2i + w2.y*u2r;
        float b3r = w3x*u3r - w3y*u3i,  b3i = w3x*u3i + w3y*u3r;
        re[i0]=u0r+b2r; im[i0]=u0i+b2i;
        re[i2]=u0r-b2r; im[i2]=u0i-b2i;
        re[i1]=u1r+b3r; im[i1]=u1i+b3i;
        re[i3]=u1r-b3r; im[i3]=u1i-b3i;
    }
    __syncthreads();
}

// ---------------------------------------------------------------- LN-apply + packed real FFT
__global__ void k_fft_fwd(const float* __restrict__ x,
                          const float* __restrict__ gamma,
                          const float* __restrict__ beta) {
    __shared__ float re[2112], im[2112];
    __shared__ float2 tw[1024];
    int t = threadIdx.x;   // 512
    int row0 = blockIdx.x*2, row1 = row0 + 1;
    int b = row0 >> 7;
    int d0 = row0 & 127, d1 = d0 + 1;
    for (int j = t; j < 1024; j += 512) {
        float sv, cv;
        __sincosf(-6.2831853071795864769f * (float)j * (1.f/2048.f), &sv, &cv);
        tw[j] = make_float2(cv, sv);
    }
    const float* xp0 = x + (size_t)row0*NG;
    const float* xp1 = x + (size_t)row1*NG;
    const float* mp  = g_mean + b*NG;
    const float* rp  = g_rstd + b*NG;
    float ga0 = gamma[d0], be0 = beta[d0], ga1 = gamma[d1], be1 = beta[d1];
    #pragma unroll
    for (int j = 0; j < 4; j++) {
        int i = t + j*512;
        float m = mp[i], r = rp[i];
        float z0 = (xp0[i]-m)*r*ga0 + be0;
        float z1 = (xp1[i]-m)*r*ga1 + be1;
        int rv = __brev(i) >> 21;
        re[IX(rv)] = z0; im[IX(rv)] = z1;
    }
    fft2048_r4(re, im, tw, 0);
    for (int k = t; k <= 1024; k += 512) {
        int km = (2048 - k) & 2047;
        float zr = re[IX(k)],  zi = im[IX(k)];
        float mr = re[IX(km)], mi = im[IX(km)];
        float4 AB = make_float4(0.5f*(zr+mr), 0.5f*(zi-mi),
                                0.5f*(zi+mi), 0.5f*(mr-zr));
        *(float4*)(&g_Xf[(size_t)k*(NB*ND) + row0]) = AB;
    }
}

// ---------------------------------------------------------------- M[f,h,d] = sum_l Phi[l,f]*Theta[l,h,d]  (fp16 out)
__global__ void k_build_M(const float* __restrict__ Phi, const float* __restrict__ Theta) {
    __shared__ float sphi[NL*32];
    int t  = threadIdx.x;
    int i  = blockIdx.x*256 + t;      // h*128+d
    int f0 = blockIdx.y*32;
    for (int idx = t; idx < NL*32; idx += 256) {
        int l = idx >> 5, ff = idx & 31;
        sphi[idx] = (f0+ff < NGF) ? Phi[l*NGF + f0 + ff] : 0.f;
    }
    __syncthreads();
    float th[NL];
    #pragma unroll
    for (int l = 0; l < NL; l++) th[l] = Theta[l*NDD + i];
    float4 acc[8];
    #pragma unroll
    for (int j = 0; j < 8; j++) acc[j] = make_float4(0.f,0.f,0.f,0.f);
    #pragma unroll
    for (int l = 0; l < NL; l++) {
        const float4* sp = (const float4*)(sphi + l*32);
        float tl = th[l];
        #pragma unroll
        for (int j = 0; j < 8; j++) {
            float4 p = sp[j];
            acc[j].x += p.x*tl; acc[j].y += p.y*tl;
            acc[j].z += p.z*tl; acc[j].w += p.w*tl;
        }
    }
    #pragma unroll
    for (int j = 0; j < 8; j++) {
        float v[4] = {acc[j].x, acc[j].y, acc[j].z, acc[j].w};
        #pragma unroll
        for (int c = 0; c < 4; c++) {
            int ff = f0 + j*4 + c;
            if (ff < NGF) g_Mh[(size_t)ff*NDD + i] = __float2half_rn(v[c]);
        }
    }
}

// ---------------------------------------------------------------- S_f: tensor-core (proven core, coalesced [f][row] stores)
#define MPAD 136
__global__ void __launch_bounds__(256) k_sf_mma() {
    __shared__ __half Msm[128*MPAD];
    __shared__ __half Xsm[16*MPAD];
    int t = threadIdx.x;       // 256
    int f = blockIdx.x;
    {
        const char* src = (const char*)(g_Mh + (size_t)f*NDD);
        unsigned sbase = (unsigned)__cvta_generic_to_shared(Msm);
        #pragma unroll
        for (int j = 0; j < 8; j++) {
            int idx = t + j*256;
            int row = idx >> 4, c = idx & 15;
            unsigned dst = sbase + row*(MPAD*2) + c*16;
            asm volatile("cp.async.cg.shared.global [%0], [%1], 16;"
                         :: "r"(dst), "l"(src + row*256 + c*16));
        }
        asm volatile("cp.async.commit_group;");
    }
    #pragma unroll
    for (int j = 0; j < 4; j++) {
        int idx = t + j*256;
        float2 v = g_Xf[(size_t)f*1024 + idx];
        int b = idx >> 7, d = idx & 127;
        Xsm[(2*b)*MPAD + d]   = __float2half_rn(v.x);
        Xsm[(2*b+1)*MPAD + d] = __float2half_rn(v.y);
    }
    asm volatile("cp.async.wait_group 0;");
    __syncthreads();

    int lane = t & 31, w = t >> 5;
    int gid = lane >> 2, tig = lane & 3;
    int h0 = w * 16;
    float c[2][4];
    #pragma unroll
    for (int j = 0; j < 2; j++)
        #pragma unroll
        for (int q = 0; q < 4; q++) c[j][q] = 0.f;

    const __half* Arow0 = Msm + (h0 + gid)*MPAD;
    const __half* Arow1 = Msm + (h0 + gid + 8)*MPAD;
    #pragma unroll
    for (int kc = 0; kc < 8; kc++) {
        int k0 = kc*16 + 2*tig;
        unsigned a[4];
        a[0] = *(const unsigned*)(Arow0 + k0);
        a[1] = *(const unsigned*)(Arow1 + k0);
        a[2] = *(const unsigned*)(Arow0 + k0 + 8);
        a[3] = *(const unsigned*)(Arow1 + k0 + 8);
        #pragma unroll
        for (int j = 0; j < 2; j++) {
            int n = j*8 + gid;
            unsigned b0 = *(const unsigned*)(Xsm + n*MPAD + k0);
            unsigned b1 = *(const unsigned*)(Xsm + n*MPAD + k0 + 8);
            mma16h(c[j], a, b0, b1);
        }
    }
    {
        float2* dst = g_Sf + (size_t)f*1024;
        #pragma unroll
        for (int j = 0; j < 2; j++) {
            int b = 4*j + tig;
            int h_lo = h0 + gid, h_hi = h_lo + 8;
            dst[b*ND + h_lo] = make_float2(c[j][0], c[j][1]);
            dst[b*ND + h_hi] = make_float2(c[j][2], c[j][3]);
        }
    }
}

// ---------------------------------------------------------------- packed irfft
__global__ void k_ifft() {
    __shared__ float re[2112], im[2112];
    __shared__ float2 tw[1024];
    int t = threadIdx.x;   // 512
    int row0 = blockIdx.x*2, row1 = row0 + 1;
    for (int j = t; j < 1024; j += 512) {
        float sv, cv;
        __sincosf(-6.2831853071795864769f * (float)j * (1.f/2048.f), &sv, &cv);
        tw[j] = make_float2(cv, sv);
    }
    #pragma unroll
    for (int j = 0; j < 4; j++) {
        int i = t + j*512;
        int src = (i <= 1024) ? i : 2048 - i;
        float4 vv = *(const float4*)(&g_Sf[(size_t)src*1024 + row0]);
        float2 v0 = make_float2(vv.x, vv.y);
        float2 v1 = make_float2(vv.z, vv.w);
        if (i > 1024) { v0.y = -v0.y; v1.y = -v1.y; }
        int rv = __brev(i) >> 21;
        re[IX(rv)] = v0.x - v1.y;
        im[IX(rv)] = v0.y + v1.x;
    }
    fft2048_r4(re, im, tw, 1);
    const float sc = 1.0f/2048.0f;
    #pragma unroll
    for (int j = 0; j < 4; j++) {
        int i = t + j*512;
        g_Sh[(size_t)row0*NG + i] = __float2half_rn(re[IX(i)]*sc);
        g_Sh[(size_t)row1*NG + i] = __float2half_rn(im[IX(i)]*sc);
    }
}

// ---------------------------------------------------------------- fp16 TC MLP, g-tile 64, cp.async double-buffered weights
// smem bytes: SsmH [64][136]h @0 (17408); HsmH [64][280]h @17408 (35840, ends 53248);
//             Wbuf 2x20480 @53248 (ends 94208); OsmF [128][66]f aliases @0 at epilogue.
#define SPADH 136
#define HPADH 280
#define WPADH 40
#define WBUF_HALF 10240
#define MLP_SMEM_BYTES 94208
__global__ void __launch_bounds__(256) k_mlp_tc(
        const float* __restrict__ x,
        const float* __restrict__ b1, const float* __restrict__ b2,
        float* __restrict__ out) {
    extern __shared__ char buf[];
    __half* SsmH = (__half*)buf;             // [64][136]
    __half* HsmH = (__half*)(buf + 17408);   // [64][280]
    __half* Wsm  = (__half*)(buf + 53248);   // 2 x WBUF_HALF halves
    float*  OsmF = (float*)buf;              // [128][66] at epilogue

    int t = threadIdx.x;           // 256
    int lane = t & 31, w = t >> 5;
    int gid = lane >> 2, tig = lane & 3;
    int b = blockIdx.y, g0 = blockIdx.x * 64;
    unsigned wsbase = (unsigned)__cvta_generic_to_shared(Wsm);

    // stage fc1 chunk 0 immediately (overlaps S-tile load)
    {
        const char* sb = (const char*)g_w1h;   // + kc*64 bytes, kc=0
        #pragma unroll
        for (int r = 0; r < 4; r++) {
            int idx = t + r*256; int row = idx >> 2, c = idx & 3;
            asm volatile("cp.async.cg.shared.global [%0], [%1], 16;"
                :: "r"(wsbase + (unsigned)(row*80 + c*16)), "l"(sb + row*256 + c*16));
        }
        asm volatile("cp.async.commit_group;");
    }

    // ---- load S tile (fp16) transposed into SsmH[g][d] ----
    {
        int d = t & 127, gq = t >> 7;
        const __half* src = g_Sh + ((size_t)(b*ND + d))*NG + g0 + gq*32;
        #pragma unroll
        for (int j = 0; j < 4; j++) {
            uint4 u = *(const uint4*)(src + j*8);
            __half2 p0 = *(__half2*)&u.x, p1 = *(__half2*)&u.y;
            __half2 p2 = *(__half2*)&u.z, p3 = *(__half2*)&u.w;
            int gg = gq*32 + j*8;
            SsmH[(gg+0)*SPADH + d] = __low2half(p0);
            SsmH[(gg+1)*SPADH + d] = __high2half(p0);
            SsmH[(gg+2)*SPADH + d] = __low2half(p1);
            SsmH[(gg+3)*SPADH + d] = __high2half(p1);
            SsmH[(gg+4)*SPADH + d] = __low2half(p2);
            SsmH[(gg+5)*SPADH + d] = __high2half(p2);
            SsmH[(gg+6)*SPADH + d] = __low2half(p3);
            SsmH[(gg+7)*SPADH + d] = __high2half(p3);
        }
    }

    // ---- fc1: Ht[64g][256h], warp w owns h in [w*32, w*32+32) ----
    float acc1[4][4][4];
    #pragma unroll
    for (int i = 0; i < 4; i++)
        #pragma unroll
        for (int jn = 0; jn < 4; jn++)
            #pragma unroll
            for (int q = 0; q < 4; q++) acc1[i][jn][q] = 0.f;
    int n0w = w * 32;
    for (int kc = 0; kc < 4; kc++) {
        asm volatile("cp.async.wait_group 0;");
        __syncthreads();
        if (kc + 1 < 4) {
            int kn = kc + 1, qn = kn & 1;
            const char* sb = (const char*)g_w1h + kn*64;
            #pragma unroll
            for (int r = 0; r < 4; r++) {
                int idx = t + r*256; int row = idx >> 2, c = idx & 3;
                asm volatile("cp.async.cg.shared.global [%0], [%1], 16;"
                    :: "r"(wsbase + (unsigned)(qn*20480 + row*80 + c*16)), "l"(sb + row*256 + c*16));
            }
            asm volatile("cp.async.commit_group;");
        }
        const __half* Wb = Wsm + (kc & 1)*WBUF_HALF;
        #pragma unroll
        for (int ks = 0; ks < 2; ks++) {
            int ka = kc*32 + ks*16 + 2*tig;
            unsigned af[4][4];
            #pragma unroll
            for (int i = 0; i < 4; i++) {
                const __half* Ar = SsmH + (i*16 + gid)*SPADH + ka;
                af[i][0] = *(const unsigned*)(Ar);
                af[i][1] = *(const unsigned*)(Ar + 8*SPADH);
                af[i][2] = *(const unsigned*)(Ar + 8);
                af[i][3] = *(const unsigned*)(Ar + 8*SPADH + 8);
            }
            int kb = ks*16 + 2*tig;
            #pragma unroll
            for (int jn = 0; jn < 4; jn++) {
                int h = n0w + jn*8 + gid;
                unsigned b0 = *(const unsigned*)(Wb + h*WPADH + kb);
                unsigned b1 = *(const unsigned*)(Wb + h*WPADH + kb + 8);
                #pragma unroll
                for (int i = 0; i < 4; i++) mma16h(acc1[i][jn], af[i], b0, b1);
            }
        }
    }
    // stage fc2 chunk 0 (buf0 free: last fc1 compute used buf1; buf0's consumers passed the kc=3 barrier)
    {
        const char* sb = (const char*)g_w2h;   // kc=0
        #pragma unroll
        for (int r = 0; r < 2; r++) {
            int idx = t + r*256; int row = idx >> 2, c = idx & 3;
            asm volatile("cp.async.cg.shared.global [%0], [%1], 16;"
                :: "r"(wsbase + (unsigned)(row*80 + c*16)), "l"(sb + row*512 + c*16));
        }
        asm volatile("cp.async.commit_group;");
    }
    // bias + GELU -> HsmH[g][h]
    #pragma unroll
    for (int jn = 0; jn < 4; jn++) {
        int n0 = n0w + jn*8;
        float bb0 = b1[n0 + 2*tig];
        float bb1 = b1[n0 + 2*tig + 1];
        #pragma unroll
        for (int i = 0; i < 4; i++) {
            int r0 = i*16 + gid;
            float g00 = gelu_exact(acc1[i][jn][0] + bb0);
            float g01 = gelu_exact(acc1[i][jn][1] + bb1);
            float g10 = gelu_exact(acc1[i][jn][2] + bb0);
            float g11 = gelu_exact(acc1[i][jn][3] + bb1);
            __half2 h01 = __floats2half2_rn(g00, g01);
            __half2 h23 = __floats2half2_rn(g10, g11);
            *(__half2*)(HsmH + r0*HPADH     + n0 + 2*tig) = h01;
            *(__half2*)(HsmH + (r0+8)*HPADH + n0 + 2*tig) = h23;
        }
    }

    // ---- fc2: outT[64g][128d], warp w owns d in [w*16, w*16+16) ----
    float acc2[4][2][4];
    #pragma unroll
    for (int i = 0; i < 4; i++)
        #pragma unroll
        for (int jn = 0; jn < 2; jn++)
            #pragma unroll
            for (int q = 0; q < 4; q++) acc2[i][jn][q] = 0.f;
    int n0w2 = w * 16;
    for (int kc = 0; kc < 8; kc++) {
        asm volatile("cp.async.wait_group 0;");
        __syncthreads();   // also publishes HsmH (GELU) on kc=0
        if (kc + 1 < 8) {
            int kn = kc + 1, qn = kn & 1;
            const char* sb = (const char*)g_w2h + kn*64;
            #pragma unroll
            for (int r = 0; r < 2; r++) {
                int idx = t + r*256; int row = idx >> 2, c = idx & 3;
                asm volatile("cp.async.cg.shared.global [%0], [%1], 16;"
                    :: "r"(wsbase + (unsigned)(qn*20480 + row*80 + c*16)), "l"(sb + row*512 + c*16));
            }
            asm volatile("cp.async.commit_group;");
        }
        const __half* Wb = Wsm + (kc & 1)*WBUF_HALF;
        #pragma unroll
        for (int ks = 0; ks < 2; ks++) {
            int ka = kc*32 + ks*16 + 2*tig;
            unsigned af[4][4];
            #pragma unroll
            for (int i = 0; i < 4; i++) {
                const __half* Ar = HsmH + (i*16 + gid)*HPADH + ka;
                af[i][0] = *(const unsigned*)(Ar);
                af[i][1] = *(const unsigned*)(Ar + 8*HPADH);
                af[i][2] = *(const unsigned*)(Ar + 8);
                af[i][3] = *(const unsigned*)(Ar + 8*HPADH + 8);
            }
            int kb = ks*16 + 2*tig;
            #pragma unroll
            for (int jn = 0; jn < 2; jn++) {
                int d = n0w2 + jn*8 + gid;
                unsigned b0 = *(const unsigned*)(Wb + d*WPADH + kb);
                unsigned b1 = *(const unsigned*)(Wb + d*WPADH + kb + 8);
                #pragma unroll
                for (int i = 0; i < 4; i++) mma16h(acc2[i][jn], af[i], b0, b1);
            }
        }
    }
    __syncthreads();   // H/S consumed -> OsmF region free
    // transpose through OsmF[d][g]  (stride 66)
    #pragma unroll
    for (int jn = 0; jn < 2; jn++) {
        int n0 = n0w2 + jn*8;
        #pragma unroll
        for (int i = 0; i < 4; i++) {
            int r0 = i*16 + gid;
            OsmF[(n0+2*tig)*66   + r0]   = acc2[i][jn][0];
            OsmF[(n0+2*tig+1)*66 + r0]   = acc2[i][jn][1];
            OsmF[(n0+2*tig)*66   + r0+8] = acc2[i][jn][2];
            OsmF[(n0+2*tig+1)*66 + r0+8] = acc2[i][jn][3];
        }
    }
    __syncthreads();
    // final: out = x + outT^T + b2 (coalesced float4 along g)
    {
        int d = t >> 1, gh = t & 1;
        float bias = b2[d];
        size_t obase = ((size_t)(b*ND + d))*NG + g0 + gh*32;
        const float* orow = OsmF + d*66 + gh*32;
        #pragma unroll
        for (int j = 0; j < 8; j++) {
            float4 xv = *(const float4*)(x + obase + j*4);
            float4 res;
            res.x = xv.x + orow[j*4]     + bias;
            res.y = xv.y + orow[j*4 + 1] + bias;
            res.z = xv.z + orow[j*4 + 2] + bias;
            res.w = xv.w + orow[j*4 + 3] + bias;
            *(float4*)(out + obase + j*4) = res;
        }
    }
}

// ----------------------------------------------------------------
extern "C" void kernel_launch(void* const* d_in, const int* in_sizes, int n_in,
                              void* d_out, int out_size) {
    const float* x     = (const float*)d_in[0];
    const float* Phi   = (const float*)d_in[1];
    const float* Theta = (const float*)d_in[2];
    const float* gam   = (const float*)d_in[3];
    const float* bet   = (const float*)d_in[4];
    const float* w1    = (const float*)d_in[5];
    const float* b1    = (const float*)d_in[6];
    const float* w2    = (const float*)d_in[7];
    const float* b2    = (const float*)d_in[8];
    float* out = (float*)d_out;

    cudaFuncSetAttribute(k_mlp_tc, cudaFuncAttributeMaxDynamicSharedMemorySize, MLP_SMEM_BYTES);

    k_cvt_w<<<128, 256>>>(w1, w2);
    k_lnstats<<<dim3(32, 8), 512>>>(x);
    k_build_M<<<dim3(64, 33), 256>>>(Phi, Theta);
    k_fft_fwd<<<512, 512>>>(x, gam, bet);
    k_sf_mma<<<NGF, 256>>>();
    k_ifft<<<512, 512>>>();
    k_mlp_tc<<<dim3(NG/64, NB), 256, MLP_SMEM_BYTES>>>(x, b1, b2, out);
}